// round 4
// baseline (speedup 1.0000x reference)
#include <cuda_runtime.h>

// Problem constants (fixed by the dataset)
#define NN    50000
#define EE    800000
#define FND   8
#define TIN   8
#define HIDN  16
#define TOUTN 4
#define SLOTS 11   // 8 initial time slices + 3 propagated h's
#define ROWF  (SLOTS * FND)   // 88 floats per node row in g_Px

// Scratch (device globals: no allocation allowed)
__device__ float g_deg[NN];
__device__ float g_dinv[NN];
__device__ float g_nself[NN];
__device__ float g_Px[(size_t)NN * ROWF];   // [n][slot][f], 17.6 MB
__device__ float g_hbuf[(size_t)NN * FND];

// ---------------------------------------------------------------------------
__global__ void k_zero_deg(int N) {
    int i = blockIdx.x * blockDim.x + threadIdx.x;
    if (i < N) g_deg[i] = 0.0f;
}

__global__ void k_deg(const int* __restrict__ ei, int E) {
    int i = blockIdx.x * blockDim.x + threadIdx.x;
    if (i < E) atomicAdd(&g_deg[ei[E + i]], 1.0f);   // dst = ei[E + e]
}

__global__ void k_norm(int N) {
    int i = blockIdx.x * blockDim.x + threadIdx.x;
    if (i < N) {
        float d = g_deg[i] + 1.0f;
        g_dinv[i]  = rsqrtf(d);
        g_nself[i] = __fdividef(1.0f, d);   // dinv*dinv
    }
}

// Px[n][t][f] = nself[n] * x[n][f][t]  — one thread per (n, t), scalars only.
__global__ void k_init_px(const float* __restrict__ x, int N) {
    int i = blockIdx.x * blockDim.x + threadIdx.x;
    int n = i >> 3;
    int t = i & 7;
    if (n >= N) return;
    float ns = g_nself[n];
    const float* xp = x + (size_t)n * 64 + t;   // x[n][f][t], stride 8 over f
    float v0 = xp[0],  v1 = xp[8],  v2 = xp[16], v3 = xp[24];
    float v4 = xp[32], v5 = xp[40], v6 = xp[48], v7 = xp[56];
    float* pr = g_Px + (size_t)n * ROWF + t * 8;
    float4 a = make_float4(ns * v0, ns * v1, ns * v2, ns * v3);
    float4 b = make_float4(ns * v4, ns * v5, ns * v6, ns * v7);
    ((float4*)pr)[0] = a;
    ((float4*)pr)[1] = b;
}

// Edge propagation of all 8 initial slices: 8 threads per edge (one per feature f)
__global__ void k_prop_init(const float* __restrict__ x, const int* __restrict__ ei, int E) {
    int i = blockIdx.x * blockDim.x + threadIdx.x;
    int e = i >> 3;
    int f = i & 7;
    if (e >= E) return;
    int s = ei[e];
    int d = ei[E + e];
    float ne = g_dinv[s] * g_dinv[d];
    const float4* xp = (const float4*)(x + (size_t)s * 64 + f * 8);
    float4 a = xp[0], b = xp[1];                    // x[s][f][t], t = 0..7
    float* base = g_Px + (size_t)d * ROWF + f;
    atomicAdd(base +  0, a.x * ne);
    atomicAdd(base +  8, a.y * ne);
    atomicAdd(base + 16, a.z * ne);
    atomicAdd(base + 24, a.w * ne);
    atomicAdd(base + 32, b.x * ne);
    atomicAdd(base + 40, b.y * ne);
    atomicAdd(base + 48, b.z * ne);
    atomicAdd(base + 56, b.w * ne);
}

// Edge propagation of h into one slot
__global__ void k_prop_h(const int* __restrict__ ei, int E, int slot) {
    int e = blockIdx.x * blockDim.x + threadIdx.x;
    if (e >= E) return;
    int s = ei[e];
    int d = ei[E + e];
    float ne = g_dinv[s] * g_dinv[d];
    const float4* hp = (const float4*)(g_hbuf + (size_t)s * 8);
    float4 a = hp[0], b = hp[1];
    float* base = g_Px + (size_t)d * ROWF + slot * 8;
    atomicAdd(base + 0, a.x * ne);
    atomicAdd(base + 1, a.y * ne);
    atomicAdd(base + 2, a.z * ne);
    atomicAdd(base + 3, a.w * ne);
    atomicAdd(base + 4, b.x * ne);
    atomicAdd(base + 5, b.y * ne);
    atomicAdd(base + 6, b.z * ne);
    atomicAdd(base + 7, b.w * ne);
}

__device__ __forceinline__ float sigmoid_f(float x) {
    return __fdividef(1.0f, 1.0f + __expf(-x));
}
__device__ __forceinline__ float tanh_f(float x) {
    float e = __expf(-2.0f * x);
    return __fdividef(1.0f - e, 1.0f + e);
}

// One 16-wide weight row FMA'd into 4 accumulators (lane owns cols q4..q4+3)
#define ROWFMA(A0, A1, A2, A3, BASE, ROW, V) do {                         \
    float4 w_ = *(const float4*)((BASE) + (ROW) * 16 + q4);               \
    A0 = fmaf((V), w_.x, A0); A1 = fmaf((V), w_.y, A1);                   \
    A2 = fmaf((V), w_.z, A2); A3 = fmaf((V), w_.w, A3); } while (0)

// Layer-1: 8 input features (qa/qb float4s) through an 8x16 weight
#define DOT8P(A0, A1, A2, A3, BASE) do {                                  \
    ROWFMA(A0, A1, A2, A3, BASE, 0, qa.x);                                \
    ROWFMA(A0, A1, A2, A3, BASE, 1, qa.y);                                \
    ROWFMA(A0, A1, A2, A3, BASE, 2, qa.z);                                \
    ROWFMA(A0, A1, A2, A3, BASE, 3, qa.w);                                \
    ROWFMA(A0, A1, A2, A3, BASE, 4, qb.x);                                \
    ROWFMA(A0, A1, A2, A3, BASE, 5, qb.y);                                \
    ROWFMA(A0, A1, A2, A3, BASE, 6, qb.z);                                \
    ROWFMA(A0, A1, A2, A3, BASE, 7, qb.w); } while (0)

// Gather 16 per-unit values spread 4-per-lane across the 4-lane node group
#define BCAST16(P, S0, S1, S2, S3) do {                                   \
    P##0  = __shfl_sync(0xffffffffu, S0, 0, 4);                           \
    P##1  = __shfl_sync(0xffffffffu, S1, 0, 4);                           \
    P##2  = __shfl_sync(0xffffffffu, S2, 0, 4);                           \
    P##3  = __shfl_sync(0xffffffffu, S3, 0, 4);                           \
    P##4  = __shfl_sync(0xffffffffu, S0, 1, 4);                           \
    P##5  = __shfl_sync(0xffffffffu, S1, 1, 4);                           \
    P##6  = __shfl_sync(0xffffffffu, S2, 1, 4);                           \
    P##7  = __shfl_sync(0xffffffffu, S3, 1, 4);                           \
    P##8  = __shfl_sync(0xffffffffu, S0, 2, 4);                           \
    P##9  = __shfl_sync(0xffffffffu, S1, 2, 4);                           \
    P##10 = __shfl_sync(0xffffffffu, S2, 2, 4);                           \
    P##11 = __shfl_sync(0xffffffffu, S3, 2, 4);                           \
    P##12 = __shfl_sync(0xffffffffu, S0, 3, 4);                           \
    P##13 = __shfl_sync(0xffffffffu, S1, 3, 4);                           \
    P##14 = __shfl_sync(0xffffffffu, S2, 3, 4);                           \
    P##15 = __shfl_sync(0xffffffffu, S3, 3, 4); } while (0)

// Sum of 16 broadcast values times rows [ROW0..ROW0+15] of a 32x16 matrix
#define DOT16(A0, A1, A2, A3, BASE, ROW0, P) do {                         \
    ROWFMA(A0, A1, A2, A3, BASE, (ROW0) + 0,  P##0);                      \
    ROWFMA(A0, A1, A2, A3, BASE, (ROW0) + 1,  P##1);                      \
    ROWFMA(A0, A1, A2, A3, BASE, (ROW0) + 2,  P##2);                      \
    ROWFMA(A0, A1, A2, A3, BASE, (ROW0) + 3,  P##3);                      \
    ROWFMA(A0, A1, A2, A3, BASE, (ROW0) + 4,  P##4);                      \
    ROWFMA(A0, A1, A2, A3, BASE, (ROW0) + 5,  P##5);                      \
    ROWFMA(A0, A1, A2, A3, BASE, (ROW0) + 6,  P##6);                      \
    ROWFMA(A0, A1, A2, A3, BASE, (ROW0) + 7,  P##7);                      \
    ROWFMA(A0, A1, A2, A3, BASE, (ROW0) + 8,  P##8);                      \
    ROWFMA(A0, A1, A2, A3, BASE, (ROW0) + 9,  P##9);                      \
    ROWFMA(A0, A1, A2, A3, BASE, (ROW0) + 10, P##10);                     \
    ROWFMA(A0, A1, A2, A3, BASE, (ROW0) + 11, P##11);                     \
    ROWFMA(A0, A1, A2, A3, BASE, (ROW0) + 12, P##12);                     \
    ROWFMA(A0, A1, A2, A3, BASE, (ROW0) + 13, P##13);                     \
    ROWFMA(A0, A1, A2, A3, BASE, (ROW0) + 14, P##14);                     \
    ROWFMA(A0, A1, A2, A3, BASE, (ROW0) + 15, P##15); } while (0)

// Fused 8-step GRU scan for one output iteration o.
// 4 lanes per node; lane q owns hidden units 4q..4q+3. Zero local arrays.
__global__ void __launch_bounds__(128)
k_scan(const float* __restrict__ att,
       const float* __restrict__ Wz, const float* __restrict__ bz,
       const float* __restrict__ Lzw, const float* __restrict__ Lzb,
       const float* __restrict__ Wr, const float* __restrict__ br,
       const float* __restrict__ Lrw, const float* __restrict__ Lrb,
       const float* __restrict__ Wh, const float* __restrict__ bh,
       const float* __restrict__ Lhw, const float* __restrict__ Lhb,
       const float* __restrict__ Wout, const float* __restrict__ bout,
       float* __restrict__ out, int N, int o)
{
    __shared__ __align__(16) float sWz[128], sWr[128], sWh[128];
    __shared__ __align__(16) float sLz[512], sLr[512], sLh[512];
    __shared__ __align__(16) float sbz[16], sbr[16], sbh[16];
    __shared__ __align__(16) float sLzb[16], sLrb[16], sLhb[16];
    __shared__ __align__(16) float sWo[128], sbo[8], sp[8];

    int tid = threadIdx.x;
    if (tid < 128) { sWz[tid] = Wz[tid]; sWr[tid] = Wr[tid]; sWh[tid] = Wh[tid]; sWo[tid] = Wout[tid]; }
    for (int i = tid; i < 512; i += 128) { sLz[i] = Lzw[i]; sLr[i] = Lrw[i]; sLh[i] = Lhw[i]; }
    if (tid < 16) {
        sbz[tid] = bz[tid]; sbr[tid] = br[tid]; sbh[tid] = bh[tid];
        sLzb[tid] = Lzb[tid]; sLrb[tid] = Lrb[tid]; sLhb[tid] = Lhb[tid];
    }
    if (tid < 8) {
        sbo[tid] = bout[tid];
        // softmax(attention) with 8-lane butterflies — no arrays
        float v = att[tid];
        float m = v;
        m = fmaxf(m, __shfl_xor_sync(0xffu, m, 1, 8));
        m = fmaxf(m, __shfl_xor_sync(0xffu, m, 2, 8));
        m = fmaxf(m, __shfl_xor_sync(0xffu, m, 4, 8));
        float e = __expf(v - m);
        float s = e;
        s += __shfl_xor_sync(0xffu, s, 1, 8);
        s += __shfl_xor_sync(0xffu, s, 2, 8);
        s += __shfl_xor_sync(0xffu, s, 4, 8);
        sp[tid] = __fdividef(e, s);
    }
    __syncthreads();

    int node = blockIdx.x * 32 + (tid >> 2);
    bool valid = (node < N);
    if (node >= N) node = N - 1;          // clamp, keep all lanes alive for shfl
    int q  = tid & 3;
    int q4 = q * 4;

    float H0 = 0.f, H1 = 0.f, H2 = 0.f, H3 = 0.f;
    float A0 = 0.f, A1 = 0.f, A2 = 0.f, A3 = 0.f;

    const float* prow = g_Px + (size_t)node * ROWF + o * 8;

#pragma unroll 1
    for (int t = 0; t < 8; t++) {
        float4 qa = ((const float4*)(prow + t * 8))[0];
        float4 qb = ((const float4*)(prow + t * 8))[1];

        float hb0, hb1, hb2, hb3, hb4, hb5, hb6, hb7,
              hb8, hb9, hb10, hb11, hb12, hb13, hb14, hb15;
        float gb0, gb1, gb2, gb3, gb4, gb5, gb6, gb7,
              gb8, gb9, gb10, gb11, gb12, gb13, gb14, gb15;
        BCAST16(hb, H0, H1, H2, H3);

        // ---- z gate ----
        float4 bv = *(const float4*)(sbz + q4);
        float g0 = bv.x, g1 = bv.y, g2 = bv.z, g3 = bv.w;
        DOT8P(g0, g1, g2, g3, sWz);
        BCAST16(gb, g0, g1, g2, g3);
        bv = *(const float4*)(sLzb + q4);
        float a0 = bv.x, a1 = bv.y, a2 = bv.z, a3 = bv.w;
        DOT16(a0, a1, a2, a3, sLz, 0,  gb);
        DOT16(a0, a1, a2, a3, sLz, 16, hb);
        float Z0 = sigmoid_f(a0), Z1 = sigmoid_f(a1), Z2 = sigmoid_f(a2), Z3 = sigmoid_f(a3);

        // ---- r gate -> H*R ----
        bv = *(const float4*)(sbr + q4);
        g0 = bv.x; g1 = bv.y; g2 = bv.z; g3 = bv.w;
        DOT8P(g0, g1, g2, g3, sWr);
        BCAST16(gb, g0, g1, g2, g3);
        bv = *(const float4*)(sLrb + q4);
        a0 = bv.x; a1 = bv.y; a2 = bv.z; a3 = bv.w;
        DOT16(a0, a1, a2, a3, sLr, 0,  gb);
        DOT16(a0, a1, a2, a3, sLr, 16, hb);
        float R0 = H0 * sigmoid_f(a0), R1 = H1 * sigmoid_f(a1);
        float R2 = H2 * sigmoid_f(a2), R3 = H3 * sigmoid_f(a3);

        // ---- h gate ----
        bv = *(const float4*)(sbh + q4);
        g0 = bv.x; g1 = bv.y; g2 = bv.z; g3 = bv.w;
        DOT8P(g0, g1, g2, g3, sWh);
        BCAST16(gb, g0, g1, g2, g3);
        BCAST16(hb, R0, R1, R2, R3);          // reuse hb for H*R broadcast
        bv = *(const float4*)(sLhb + q4);
        a0 = bv.x; a1 = bv.y; a2 = bv.z; a3 = bv.w;
        DOT16(a0, a1, a2, a3, sLh, 0,  gb);
        DOT16(a0, a1, a2, a3, sLh, 16, hb);
        float T0 = tanh_f(a0), T1 = tanh_f(a1), T2 = tanh_f(a2), T3 = tanh_f(a3);

        float pt = sp[t];
        H0 = Z0 * H0 + (1.0f - Z0) * T0;  A0 = fmaf(pt, H0, A0);
        H1 = Z1 * H1 + (1.0f - Z1) * T1;  A1 = fmaf(pt, H1, A1);
        H2 = Z2 * H2 + (1.0f - Z2) * T2;  A2 = fmaf(pt, H2, A2);
        H3 = Z3 * H3 + (1.0f - Z3) * T3;  A3 = fmaf(pt, H3, A3);
    }

    // Output projection: ho = relu(Ha) @ Wout + bout (16x8), reduced over 4 lanes
    float r0 = fmaxf(A0, 0.f), r1 = fmaxf(A1, 0.f);
    float r2 = fmaxf(A2, 0.f), r3 = fmaxf(A3, 0.f);
#define OUTF(F) (fmaf(r0, sWo[(q4 + 0) * 8 + (F)],                        \
                 fmaf(r1, sWo[(q4 + 1) * 8 + (F)],                        \
                 fmaf(r2, sWo[(q4 + 2) * 8 + (F)],                        \
                      r3 * sWo[(q4 + 3) * 8 + (F)]))))
    float o0 = OUTF(0), o1 = OUTF(1), o2 = OUTF(2), o3 = OUTF(3);
    float o4 = OUTF(4), o5 = OUTF(5), o6 = OUTF(6), o7 = OUTF(7);
#undef OUTF
    o0 += __shfl_xor_sync(0xffffffffu, o0, 1, 4);
    o1 += __shfl_xor_sync(0xffffffffu, o1, 1, 4);
    o2 += __shfl_xor_sync(0xffffffffu, o2, 1, 4);
    o3 += __shfl_xor_sync(0xffffffffu, o3, 1, 4);
    o4 += __shfl_xor_sync(0xffffffffu, o4, 1, 4);
    o5 += __shfl_xor_sync(0xffffffffu, o5, 1, 4);
    o6 += __shfl_xor_sync(0xffffffffu, o6, 1, 4);
    o7 += __shfl_xor_sync(0xffffffffu, o7, 1, 4);
    o0 += __shfl_xor_sync(0xffffffffu, o0, 2, 4);
    o1 += __shfl_xor_sync(0xffffffffu, o1, 2, 4);
    o2 += __shfl_xor_sync(0xffffffffu, o2, 2, 4);
    o3 += __shfl_xor_sync(0xffffffffu, o3, 2, 4);
    o4 += __shfl_xor_sync(0xffffffffu, o4, 2, 4);
    o5 += __shfl_xor_sync(0xffffffffu, o5, 2, 4);
    o6 += __shfl_xor_sync(0xffffffffu, o6, 2, 4);
    o7 += __shfl_xor_sync(0xffffffffu, o7, 2, 4);
    o0 += sbo[0]; o1 += sbo[1]; o2 += sbo[2]; o3 += sbo[3];
    o4 += sbo[4]; o5 += sbo[5]; o6 += sbo[6]; o7 += sbo[7];

    // lane q writes features 2q and 2q+1
    float wa, wb2;
    if      (q == 0) { wa = o0; wb2 = o1; }
    else if (q == 1) { wa = o2; wb2 = o3; }
    else if (q == 2) { wa = o4; wb2 = o5; }
    else             { wa = o6; wb2 = o7; }

    if (valid) {
        int f = 2 * q;
        float* op = out + (size_t)node * 32 + o;     // out[n][f][o], shape (N,8,4)
        op[f * 4]       = wa;
        op[(f + 1) * 4] = wb2;
        if (o < 3) {
            float ns = g_nself[node];
            float* hb = g_hbuf + (size_t)node * 8;
            float* ps = g_Px + (size_t)node * ROWF + (8 + o) * 8;
            hb[f]     = wa;
            hb[f + 1] = wb2;
            ps[f]     = ns * wa;
            ps[f + 1] = ns * wb2;
        }
    }
}

// ---------------------------------------------------------------------------
extern "C" void kernel_launch(void* const* d_in, const int* in_sizes, int n_in,
                              void* d_out, int out_size)
{
    const float* x    = (const float*)d_in[0];
    const int*   ei   = (const int*)d_in[1];
    const float* att  = (const float*)d_in[2];
    const float* Wz   = (const float*)d_in[3];
    const float* bz   = (const float*)d_in[4];
    const float* Lzw  = (const float*)d_in[5];
    const float* Lzb  = (const float*)d_in[6];
    const float* Wr   = (const float*)d_in[7];
    const float* br   = (const float*)d_in[8];
    const float* Lrw  = (const float*)d_in[9];
    const float* Lrb  = (const float*)d_in[10];
    const float* Wh   = (const float*)d_in[11];
    const float* bh   = (const float*)d_in[12];
    const float* Lhw  = (const float*)d_in[13];
    const float* Lhb  = (const float*)d_in[14];
    const float* Wout = (const float*)d_in[15];
    const float* bout = (const float*)d_in[16];
    float* out = (float*)d_out;

    int N = in_sizes[0] / (FND * TIN);
    int E = in_sizes[1] / 2;
    if (N > NN) N = NN;   // static scratch capacity guard
    if (E > EE) E = EE;

    const int TB = 256;
    k_zero_deg<<<(N + TB - 1) / TB, TB>>>(N);
    k_deg<<<(E + TB - 1) / TB, TB>>>(ei, E);
    k_norm<<<(N + TB - 1) / TB, TB>>>(N);
    {
        long long tot = (long long)N * 8;
        k_init_px<<<(int)((tot + TB - 1) / TB), TB>>>(x, N);
    }
    {
        long long tot = (long long)E * 8;
        k_prop_init<<<(int)((tot + TB - 1) / TB), TB>>>(x, ei, E);
    }

    for (int o = 0; o < TOUTN; o++) {
        k_scan<<<(N + 31) / 32, 128>>>(att, Wz, bz, Lzw, Lzb, Wr, br, Lrw, Lrb,
                                       Wh, bh, Lhw, Lhb, Wout, bout, out, N, o);
        if (o < 3) {
            k_prop_h<<<(E + TB - 1) / TB, TB>>>(ei, E, 8 + o);
        }
    }
}

// round 6
// speedup vs baseline: 1.3016x; 1.3016x over previous
#include <cuda_runtime.h>

// Problem constants (fixed by the dataset)
#define NN    50000
#define EE    800000
#define FND   8
#define TIN   8
#define HIDN  16
#define TOUTN 4
#define SLOTS 11   // 8 initial time slices + 3 propagated h's
#define ROWF  (SLOTS * FND)   // 88 floats per node row in g_Px

// Scratch (device globals: no allocation allowed)
__device__ float g_deg[NN];
__device__ float g_dinv[NN];
__device__ float g_nself[NN];
__device__ float g_Px[(size_t)NN * ROWF];   // [n][slot][f], 17.6 MB
__device__ float g_hbuf[(size_t)NN * FND];

// ---------------------------------------------------------------------------
__global__ void k_zero_deg(int N) {
    int i = blockIdx.x * blockDim.x + threadIdx.x;
    if (i < N) g_deg[i] = 0.0f;
}

__global__ void k_deg(const int* __restrict__ ei, int E) {
    int i = blockIdx.x * blockDim.x + threadIdx.x;
    if (i < E) atomicAdd(&g_deg[ei[E + i]], 1.0f);   // dst = ei[E + e]
}

__global__ void k_norm(int N) {
    int i = blockIdx.x * blockDim.x + threadIdx.x;
    if (i < N) {
        float d = g_deg[i] + 1.0f;
        g_dinv[i]  = rsqrtf(d);
        g_nself[i] = __fdividef(1.0f, d);   // dinv*dinv
    }
}

// Px[n][t][f] = nself[n] * x[n][f][t]  — one thread per (n, t), scalars only.
__global__ void k_init_px(const float* __restrict__ x, int N) {
    int i = blockIdx.x * blockDim.x + threadIdx.x;
    int n = i >> 3;
    int t = i & 7;
    if (n >= N) return;
    float ns = g_nself[n];
    const float* xp = x + (size_t)n * 64 + t;   // x[n][f][t], stride 8 over f
    float v0 = xp[0],  v1 = xp[8],  v2 = xp[16], v3 = xp[24];
    float v4 = xp[32], v5 = xp[40], v6 = xp[48], v7 = xp[56];
    float* pr = g_Px + (size_t)n * ROWF + t * 8;
    float4 a = make_float4(ns * v0, ns * v1, ns * v2, ns * v3);
    float4 b = make_float4(ns * v4, ns * v5, ns * v6, ns * v7);
    ((float4*)pr)[0] = a;
    ((float4*)pr)[1] = b;
}

// Edge propagation of all 8 initial slices: 8 threads per edge (one per feature f)
// Scalar f32 atomics — the fast REDG path on sm_103a (vector RED hangs under contention).
__global__ void k_prop_init(const float* __restrict__ x, const int* __restrict__ ei, int E) {
    int i = blockIdx.x * blockDim.x + threadIdx.x;
    int e = i >> 3;
    int f = i & 7;
    if (e >= E) return;
    int s = ei[e];
    int d = ei[E + e];
    float ne = g_dinv[s] * g_dinv[d];
    const float4* xp = (const float4*)(x + (size_t)s * 64 + f * 8);
    float4 a = xp[0], b = xp[1];                    // x[s][f][t], t = 0..7
    float* base = g_Px + (size_t)d * ROWF + f;
    atomicAdd(base +  0, a.x * ne);
    atomicAdd(base +  8, a.y * ne);
    atomicAdd(base + 16, a.z * ne);
    atomicAdd(base + 24, a.w * ne);
    atomicAdd(base + 32, b.x * ne);
    atomicAdd(base + 40, b.y * ne);
    atomicAdd(base + 48, b.z * ne);
    atomicAdd(base + 56, b.w * ne);
}

// Edge propagation of h into one slot (scalar atomics)
__global__ void k_prop_h(const int* __restrict__ ei, int E, int slot) {
    int e = blockIdx.x * blockDim.x + threadIdx.x;
    if (e >= E) return;
    int s = ei[e];
    int d = ei[E + e];
    float ne = g_dinv[s] * g_dinv[d];
    const float4* hp = (const float4*)(g_hbuf + (size_t)s * 8);
    float4 a = hp[0], b = hp[1];
    float* base = g_Px + (size_t)d * ROWF + slot * 8;
    atomicAdd(base + 0, a.x * ne);
    atomicAdd(base + 1, a.y * ne);
    atomicAdd(base + 2, a.z * ne);
    atomicAdd(base + 3, a.w * ne);
    atomicAdd(base + 4, b.x * ne);
    atomicAdd(base + 5, b.y * ne);
    atomicAdd(base + 6, b.z * ne);
    atomicAdd(base + 7, b.w * ne);
}

__device__ __forceinline__ float sigmoid_f(float x) {
    return __fdividef(1.0f, 1.0f + __expf(-x));
}
__device__ __forceinline__ float tanh_f(float x) {
    float e = __expf(-2.0f * x);
    return __fdividef(1.0f - e, 1.0f + e);
}

// One 16B weight load feeds BOTH nodes (8 FMAs per LDS.128).
// Gate accumulators are fixed names cA0..cA3 / cB0..cB3.
#define ROWFMA2(BASE, ROW, VA, VB) do {                                   \
    float4 w_ = *(const float4*)((BASE) + (ROW) * 16 + q4);               \
    cA0 = fmaf((VA), w_.x, cA0); cA1 = fmaf((VA), w_.y, cA1);             \
    cA2 = fmaf((VA), w_.z, cA2); cA3 = fmaf((VA), w_.w, cA3);             \
    cB0 = fmaf((VB), w_.x, cB0); cB1 = fmaf((VB), w_.y, cB1);             \
    cB2 = fmaf((VB), w_.z, cB2); cB3 = fmaf((VB), w_.w, cB3); } while (0)

// Layer-1: 8 input features through an 8x16 weight, two nodes at once
#define DOT8P2(BASE) do {                                                 \
    ROWFMA2(BASE, 0, qaA.x, qaB.x);                                       \
    ROWFMA2(BASE, 1, qaA.y, qaB.y);                                       \
    ROWFMA2(BASE, 2, qaA.z, qaB.z);                                       \
    ROWFMA2(BASE, 3, qaA.w, qaB.w);                                       \
    ROWFMA2(BASE, 4, qbA.x, qbB.x);                                       \
    ROWFMA2(BASE, 5, qbA.y, qbB.y);                                       \
    ROWFMA2(BASE, 6, qbA.z, qbB.z);                                       \
    ROWFMA2(BASE, 7, qbA.w, qbB.w); } while (0)

// Gather 16 per-unit values spread 4-per-lane across the 4-lane node group
#define BCAST16(P, S0, S1, S2, S3) do {                                   \
    P##0  = __shfl_sync(0xffffffffu, S0, 0, 4);                           \
    P##1  = __shfl_sync(0xffffffffu, S1, 0, 4);                           \
    P##2  = __shfl_sync(0xffffffffu, S2, 0, 4);                           \
    P##3  = __shfl_sync(0xffffffffu, S3, 0, 4);                           \
    P##4  = __shfl_sync(0xffffffffu, S0, 1, 4);                           \
    P##5  = __shfl_sync(0xffffffffu, S1, 1, 4);                           \
    P##6  = __shfl_sync(0xffffffffu, S2, 1, 4);                           \
    P##7  = __shfl_sync(0xffffffffu, S3, 1, 4);                           \
    P##8  = __shfl_sync(0xffffffffu, S0, 2, 4);                           \
    P##9  = __shfl_sync(0xffffffffu, S1, 2, 4);                           \
    P##10 = __shfl_sync(0xffffffffu, S2, 2, 4);                           \
    P##11 = __shfl_sync(0xffffffffu, S3, 2, 4);                           \
    P##12 = __shfl_sync(0xffffffffu, S0, 3, 4);                           \
    P##13 = __shfl_sync(0xffffffffu, S1, 3, 4);                           \
    P##14 = __shfl_sync(0xffffffffu, S2, 3, 4);                           \
    P##15 = __shfl_sync(0xffffffffu, S3, 3, 4); } while (0)

// 16 broadcast values (per node) times rows [ROW0..ROW0+15], two nodes at once
#define DOT16_2(BASE, ROW0, PA, PB) do {                                  \
    ROWFMA2(BASE, (ROW0) + 0,  PA##0,  PB##0);                            \
    ROWFMA2(BASE, (ROW0) + 1,  PA##1,  PB##1);                            \
    ROWFMA2(BASE, (ROW0) + 2,  PA##2,  PB##2);                            \
    ROWFMA2(BASE, (ROW0) + 3,  PA##3,  PB##3);                            \
    ROWFMA2(BASE, (ROW0) + 4,  PA##4,  PB##4);                            \
    ROWFMA2(BASE, (ROW0) + 5,  PA##5,  PB##5);                            \
    ROWFMA2(BASE, (ROW0) + 6,  PA##6,  PB##6);                            \
    ROWFMA2(BASE, (ROW0) + 7,  PA##7,  PB##7);                            \
    ROWFMA2(BASE, (ROW0) + 8,  PA##8,  PB##8);                            \
    ROWFMA2(BASE, (ROW0) + 9,  PA##9,  PB##9);                            \
    ROWFMA2(BASE, (ROW0) + 10, PA##10, PB##10);                           \
    ROWFMA2(BASE, (ROW0) + 11, PA##11, PB##11);                           \
    ROWFMA2(BASE, (ROW0) + 12, PA##12, PB##12);                           \
    ROWFMA2(BASE, (ROW0) + 13, PA##13, PB##13);                           \
    ROWFMA2(BASE, (ROW0) + 14, PA##14, PB##14);                           \
    ROWFMA2(BASE, (ROW0) + 15, PA##15, PB##15); } while (0)

// Per-node output projection + stores (uses q, q4, sWo, sbo, out, o, N scope vars)
#define EPILOGUE(AX0, AX1, AX2, AX3, NODE, VALID) do {                    \
    float r0 = fmaxf(AX0, 0.f), r1 = fmaxf(AX1, 0.f);                     \
    float r2 = fmaxf(AX2, 0.f), r3 = fmaxf(AX3, 0.f);                     \
    float o0 = OUTF(0), o1 = OUTF(1), o2 = OUTF(2), o3 = OUTF(3);         \
    float o4 = OUTF(4), o5 = OUTF(5), o6 = OUTF(6), o7 = OUTF(7);         \
    o0 += __shfl_xor_sync(0xffffffffu, o0, 1, 4);                         \
    o1 += __shfl_xor_sync(0xffffffffu, o1, 1, 4);                         \
    o2 += __shfl_xor_sync(0xffffffffu, o2, 1, 4);                         \
    o3 += __shfl_xor_sync(0xffffffffu, o3, 1, 4);                         \
    o4 += __shfl_xor_sync(0xffffffffu, o4, 1, 4);                         \
    o5 += __shfl_xor_sync(0xffffffffu, o5, 1, 4);                         \
    o6 += __shfl_xor_sync(0xffffffffu, o6, 1, 4);                         \
    o7 += __shfl_xor_sync(0xffffffffu, o7, 1, 4);                         \
    o0 += __shfl_xor_sync(0xffffffffu, o0, 2, 4);                         \
    o1 += __shfl_xor_sync(0xffffffffu, o1, 2, 4);                         \
    o2 += __shfl_xor_sync(0xffffffffu, o2, 2, 4);                         \
    o3 += __shfl_xor_sync(0xffffffffu, o3, 2, 4);                         \
    o4 += __shfl_xor_sync(0xffffffffu, o4, 2, 4);                         \
    o5 += __shfl_xor_sync(0xffffffffu, o5, 2, 4);                         \
    o6 += __shfl_xor_sync(0xffffffffu, o6, 2, 4);                         \
    o7 += __shfl_xor_sync(0xffffffffu, o7, 2, 4);                         \
    o0 += sbo[0]; o1 += sbo[1]; o2 += sbo[2]; o3 += sbo[3];               \
    o4 += sbo[4]; o5 += sbo[5]; o6 += sbo[6]; o7 += sbo[7];               \
    float wa, wb2;                                                        \
    if      (q == 0) { wa = o0; wb2 = o1; }                               \
    else if (q == 1) { wa = o2; wb2 = o3; }                               \
    else if (q == 2) { wa = o4; wb2 = o5; }                               \
    else             { wa = o6; wb2 = o7; }                               \
    if (VALID) {                                                          \
        int f = 2 * q;                                                    \
        float* op = out + (size_t)(NODE) * 32 + o;                        \
        op[f * 4]       = wa;                                             \
        op[(f + 1) * 4] = wb2;                                            \
        if (o < 3) {                                                      \
            float ns = g_nself[(NODE)];                                   \
            float* hbp = g_hbuf + (size_t)(NODE) * 8;                     \
            float* psp = g_Px + (size_t)(NODE) * ROWF + (8 + o) * 8;      \
            hbp[f]     = wa;                                              \
            hbp[f + 1] = wb2;                                             \
            psp[f]     = ns * wa;                                         \
            psp[f + 1] = ns * wb2;                                        \
        }                                                                 \
    }                                                                     \
} while (0)

// Fused 8-step GRU scan for one output iteration o.
// 4 lanes per node, TWO nodes per lane (block covers 64 nodes).
__global__ void __launch_bounds__(128)
k_scan(const float* __restrict__ att,
       const float* __restrict__ Wz, const float* __restrict__ bz,
       const float* __restrict__ Lzw, const float* __restrict__ Lzb,
       const float* __restrict__ Wr, const float* __restrict__ br,
       const float* __restrict__ Lrw, const float* __restrict__ Lrb,
       const float* __restrict__ Wh, const float* __restrict__ bh,
       const float* __restrict__ Lhw, const float* __restrict__ Lhb,
       const float* __restrict__ Wout, const float* __restrict__ bout,
       float* __restrict__ out, int N, int o)
{
    __shared__ __align__(16) float sWz[128], sWr[128], sWh[128];
    __shared__ __align__(16) float sLz[512], sLr[512], sLh[512];
    __shared__ __align__(16) float sbz[16], sbr[16], sbh[16];
    __shared__ __align__(16) float sLzb[16], sLrb[16], sLhb[16];
    __shared__ __align__(16) float sWo[128], sbo[8], sp[8];

    int tid = threadIdx.x;
    if (tid < 128) { sWz[tid] = Wz[tid]; sWr[tid] = Wr[tid]; sWh[tid] = Wh[tid]; sWo[tid] = Wout[tid]; }
    for (int i = tid; i < 512; i += 128) { sLz[i] = Lzw[i]; sLr[i] = Lrw[i]; sLh[i] = Lhw[i]; }
    if (tid < 16) {
        sbz[tid] = bz[tid]; sbr[tid] = br[tid]; sbh[tid] = bh[tid];
        sLzb[tid] = Lzb[tid]; sLrb[tid] = Lrb[tid]; sLhb[tid] = Lhb[tid];
    }
    if (tid < 8) {
        sbo[tid] = bout[tid];
        // softmax(attention) with 8-lane butterflies — no arrays
        float v = att[tid];
        float m = v;
        m = fmaxf(m, __shfl_xor_sync(0xffu, m, 1, 8));
        m = fmaxf(m, __shfl_xor_sync(0xffu, m, 2, 8));
        m = fmaxf(m, __shfl_xor_sync(0xffu, m, 4, 8));
        float e = __expf(v - m);
        float s = e;
        s += __shfl_xor_sync(0xffu, s, 1, 8);
        s += __shfl_xor_sync(0xffu, s, 2, 8);
        s += __shfl_xor_sync(0xffu, s, 4, 8);
        sp[tid] = __fdividef(e, s);
    }
    __syncthreads();

    int g = tid >> 2;                       // lane group 0..31
    int nodeA = blockIdx.x * 64 + g;
    int nodeB = nodeA + 32;
    bool validA = (nodeA < N);
    bool validB = (nodeB < N);
    if (nodeA >= N) nodeA = N - 1;          // clamp, keep all lanes alive for shfl
    if (nodeB >= N) nodeB = N - 1;
    int q  = tid & 3;
    int q4 = q * 4;

    float HA0 = 0.f, HA1 = 0.f, HA2 = 0.f, HA3 = 0.f;
    float HB0 = 0.f, HB1 = 0.f, HB2 = 0.f, HB3 = 0.f;
    float AA0 = 0.f, AA1 = 0.f, AA2 = 0.f, AA3 = 0.f;
    float AB0 = 0.f, AB1 = 0.f, AB2 = 0.f, AB3 = 0.f;

    const float* prowA = g_Px + (size_t)nodeA * ROWF + o * 8;
    const float* prowB = g_Px + (size_t)nodeB * ROWF + o * 8;

#pragma unroll 1
    for (int t = 0; t < 8; t++) {
        float4 qaA = ((const float4*)(prowA + t * 8))[0];
        float4 qbA = ((const float4*)(prowA + t * 8))[1];
        float4 qaB = ((const float4*)(prowB + t * 8))[0];
        float4 qbB = ((const float4*)(prowB + t * 8))[1];

        float hbA0, hbA1, hbA2, hbA3, hbA4, hbA5, hbA6, hbA7,
              hbA8, hbA9, hbA10, hbA11, hbA12, hbA13, hbA14, hbA15;
        float hbB0, hbB1, hbB2, hbB3, hbB4, hbB5, hbB6, hbB7,
              hbB8, hbB9, hbB10, hbB11, hbB12, hbB13, hbB14, hbB15;
        float gbA0, gbA1, gbA2, gbA3, gbA4, gbA5, gbA6, gbA7,
              gbA8, gbA9, gbA10, gbA11, gbA12, gbA13, gbA14, gbA15;
        float gbB0, gbB1, gbB2, gbB3, gbB4, gbB5, gbB6, gbB7,
              gbB8, gbB9, gbB10, gbB11, gbB12, gbB13, gbB14, gbB15;
        BCAST16(hbA, HA0, HA1, HA2, HA3);
        BCAST16(hbB, HB0, HB1, HB2, HB3);

        float ZA0, ZA1, ZA2, ZA3, ZB0, ZB1, ZB2, ZB3;
        float RA0, RA1, RA2, RA3, RB0, RB1, RB2, RB3;
        float TA0, TA1, TA2, TA3, TB0, TB1, TB2, TB3;

        {   // ---- z gate ----
            float4 bv = *(const float4*)(sbz + q4);
            float cA0 = bv.x, cA1 = bv.y, cA2 = bv.z, cA3 = bv.w;
            float cB0 = bv.x, cB1 = bv.y, cB2 = bv.z, cB3 = bv.w;
            DOT8P2(sWz);
            BCAST16(gbA, cA0, cA1, cA2, cA3);
            BCAST16(gbB, cB0, cB1, cB2, cB3);
            bv = *(const float4*)(sLzb + q4);
            cA0 = bv.x; cA1 = bv.y; cA2 = bv.z; cA3 = bv.w;
            cB0 = bv.x; cB1 = bv.y; cB2 = bv.z; cB3 = bv.w;
            DOT16_2(sLz, 0,  gbA, gbB);
            DOT16_2(sLz, 16, hbA, hbB);
            ZA0 = sigmoid_f(cA0); ZA1 = sigmoid_f(cA1); ZA2 = sigmoid_f(cA2); ZA3 = sigmoid_f(cA3);
            ZB0 = sigmoid_f(cB0); ZB1 = sigmoid_f(cB1); ZB2 = sigmoid_f(cB2); ZB3 = sigmoid_f(cB3);
        }
        {   // ---- r gate -> H*R ----
            float4 bv = *(const float4*)(sbr + q4);
            float cA0 = bv.x, cA1 = bv.y, cA2 = bv.z, cA3 = bv.w;
            float cB0 = bv.x, cB1 = bv.y, cB2 = bv.z, cB3 = bv.w;
            DOT8P2(sWr);
            BCAST16(gbA, cA0, cA1, cA2, cA3);
            BCAST16(gbB, cB0, cB1, cB2, cB3);
            bv = *(const float4*)(sLrb + q4);
            cA0 = bv.x; cA1 = bv.y; cA2 = bv.z; cA3 = bv.w;
            cB0 = bv.x; cB1 = bv.y; cB2 = bv.z; cB3 = bv.w;
            DOT16_2(sLr, 0,  gbA, gbB);
            DOT16_2(sLr, 16, hbA, hbB);
            RA0 = HA0 * sigmoid_f(cA0); RA1 = HA1 * sigmoid_f(cA1);
            RA2 = HA2 * sigmoid_f(cA2); RA3 = HA3 * sigmoid_f(cA3);
            RB0 = HB0 * sigmoid_f(cB0); RB1 = HB1 * sigmoid_f(cB1);
            RB2 = HB2 * sigmoid_f(cB2); RB3 = HB3 * sigmoid_f(cB3);
        }
        {   // ---- h gate ----
            float4 bv = *(const float4*)(sbh + q4);
            float cA0 = bv.x, cA1 = bv.y, cA2 = bv.z, cA3 = bv.w;
            float cB0 = bv.x, cB1 = bv.y, cB2 = bv.z, cB3 = bv.w;
            DOT8P2(sWh);
            BCAST16(gbA, cA0, cA1, cA2, cA3);
            BCAST16(gbB, cB0, cB1, cB2, cB3);
            BCAST16(hbA, RA0, RA1, RA2, RA3);   // reuse hb regs for H*R broadcast
            BCAST16(hbB, RB0, RB1, RB2, RB3);
            bv = *(const float4*)(sLhb + q4);
            cA0 = bv.x; cA1 = bv.y; cA2 = bv.z; cA3 = bv.w;
            cB0 = bv.x; cB1 = bv.y; cB2 = bv.z; cB3 = bv.w;
            DOT16_2(sLh, 0,  gbA, gbB);
            DOT16_2(sLh, 16, hbA, hbB);
            TA0 = tanh_f(cA0); TA1 = tanh_f(cA1); TA2 = tanh_f(cA2); TA3 = tanh_f(cA3);
            TB0 = tanh_f(cB0); TB1 = tanh_f(cB1); TB2 = tanh_f(cB2); TB3 = tanh_f(cB3);
        }

        float pt = sp[t];
        HA0 = ZA0 * HA0 + (1.0f - ZA0) * TA0;  AA0 = fmaf(pt, HA0, AA0);
        HA1 = ZA1 * HA1 + (1.0f - ZA1) * TA1;  AA1 = fmaf(pt, HA1, AA1);
        HA2 = ZA2 * HA2 + (1.0f - ZA2) * TA2;  AA2 = fmaf(pt, HA2, AA2);
        HA3 = ZA3 * HA3 + (1.0f - ZA3) * TA3;  AA3 = fmaf(pt, HA3, AA3);
        HB0 = ZB0 * HB0 + (1.0f - ZB0) * TB0;  AB0 = fmaf(pt, HB0, AB0);
        HB1 = ZB1 * HB1 + (1.0f - ZB1) * TB1;  AB1 = fmaf(pt, HB1, AB1);
        HB2 = ZB2 * HB2 + (1.0f - ZB2) * TB2;  AB2 = fmaf(pt, HB2, AB2);
        HB3 = ZB3 * HB3 + (1.0f - ZB3) * TB3;  AB3 = fmaf(pt, HB3, AB3);
    }

#define OUTF(F) (fmaf(r0, sWo[(q4 + 0) * 8 + (F)],                        \
                 fmaf(r1, sWo[(q4 + 1) * 8 + (F)],                        \
                 fmaf(r2, sWo[(q4 + 2) * 8 + (F)],                        \
                      r3 * sWo[(q4 + 3) * 8 + (F)]))))
    EPILOGUE(AA0, AA1, AA2, AA3, nodeA, validA);
    EPILOGUE(AB0, AB1, AB2, AB3, nodeB, validB);
#undef OUTF
}

// ---------------------------------------------------------------------------
extern "C" void kernel_launch(void* const* d_in, const int* in_sizes, int n_in,
                              void* d_out, int out_size)
{
    const float* x    = (const float*)d_in[0];
    const int*   ei   = (const int*)d_in[1];
    const float* att  = (const float*)d_in[2];
    const float* Wz   = (const float*)d_in[3];
    const float* bz   = (const float*)d_in[4];
    const float* Lzw  = (const float*)d_in[5];
    const float* Lzb  = (const float*)d_in[6];
    const float* Wr   = (const float*)d_in[7];
    const float* br   = (const float*)d_in[8];
    const float* Lrw  = (const float*)d_in[9];
    const float* Lrb  = (const float*)d_in[10];
    const float* Wh   = (const float*)d_in[11];
    const float* bh   = (const float*)d_in[12];
    const float* Lhw  = (const float*)d_in[13];
    const float* Lhb  = (const float*)d_in[14];
    const float* Wout = (const float*)d_in[15];
    const float* bout = (const float*)d_in[16];
    float* out = (float*)d_out;

    int N = in_sizes[0] / (FND * TIN);
    int E = in_sizes[1] / 2;
    if (N > NN) N = NN;   // static scratch capacity guard
    if (E > EE) E = EE;

    const int TB = 256;
    k_zero_deg<<<(N + TB - 1) / TB, TB>>>(N);
    k_deg<<<(E + TB - 1) / TB, TB>>>(ei, E);
    k_norm<<<(N + TB - 1) / TB, TB>>>(N);
    {
        long long tot = (long long)N * 8;
        k_init_px<<<(int)((tot + TB - 1) / TB), TB>>>(x, N);
    }
    {
        long long tot = (long long)E * 8;
        k_prop_init<<<(int)((tot + TB - 1) / TB), TB>>>(x, ei, E);
    }

    for (int o = 0; o < TOUTN; o++) {
        k_scan<<<(N + 63) / 64, 128>>>(att, Wz, bz, Lzw, Lzb, Wr, br, Lrw, Lrb,
                                       Wh, bh, Lhw, Lhb, Wout, bout, out, N, o);
        if (o < 3) {
            k_prop_h<<<(E + TB - 1) / TB, TB>>>(ei, E, 8 + o);
        }
    }
}

// round 7
// speedup vs baseline: 1.5194x; 1.1673x over previous
#include <cuda_runtime.h>

// Problem constants (fixed by the dataset)
#define NN    50000
#define EE    800000
#define FND   8
#define TIN   8
#define HIDN  16
#define TOUTN 4
#define SLOTS 11   // 8 initial time slices + 3 propagated h's
#define ROWF  (SLOTS * FND)   // 88 floats per node row in g_Px

// Scratch (device globals: no allocation allowed)
__device__ int   g_cnt[NN];
__device__ int   g_pos[NN];
__device__ int   g_off[NN + 1];
__device__ int   g_csr[EE];              // src list grouped by dst
__device__ float g_dinv[NN];
__device__ float g_nself[NN];
__device__ float g_Px[(size_t)NN * ROWF];   // [n][slot][f], 17.6 MB
__device__ float g_hbuf[(size_t)NN * FND];

// ---------------------------------------------------------------------------
__global__ void k_zero_int(int N) {
    int i = blockIdx.x * blockDim.x + threadIdx.x;
    if (i < N) { g_cnt[i] = 0; g_pos[i] = 0; }
}

__global__ void k_cnt(const int* __restrict__ ei, int E) {
    int i = blockIdx.x * blockDim.x + threadIdx.x;
    if (i < E) atomicAdd(&g_cnt[ei[E + i]], 1);   // dst = ei[E + e]
}

__global__ void k_norm(int N) {
    int i = blockIdx.x * blockDim.x + threadIdx.x;
    if (i < N) {
        float d = (float)g_cnt[i] + 1.0f;
        g_dinv[i]  = rsqrtf(d);
        g_nself[i] = __fdividef(1.0f, d);   // dinv*dinv
    }
}

// Exclusive prefix sum of g_cnt -> g_off, single block of 1024 threads.
__global__ void k_prefix(int N) {
    __shared__ int ssum[1024];
    int tid = threadIdx.x;
    int per = (N + 1023) >> 10;
    int start = tid * per;
    int end = start + per; if (end > N) end = N;
    int s = 0;
    for (int i = start; i < end && i >= 0; i++) s += g_cnt[i];
    ssum[tid] = s;
    __syncthreads();
    // Hillis-Steele inclusive scan over per-thread sums
    for (int d = 1; d < 1024; d <<= 1) {
        int v = (tid >= d) ? ssum[tid - d] : 0;
        __syncthreads();
        ssum[tid] += v;
        __syncthreads();
    }
    int run = ssum[tid] - s;   // exclusive base for this chunk
    for (int i = start; i < end && i >= 0; i++) { g_off[i] = run; run += g_cnt[i]; }
    if (end >= N && start <= N) g_off[N] = ssum[1023] - (ssum[1023] - run) * 0;  // run == total here
}

__global__ void k_scatter(const int* __restrict__ ei, int E) {
    int e = blockIdx.x * blockDim.x + threadIdx.x;
    if (e >= E) return;
    int d = ei[E + e];
    int p = atomicAdd(&g_pos[d], 1);
    g_csr[g_off[d] + p] = ei[e];
}

// Gather-based propagation of all 8 initial slices + self term.
// 8 threads per node (one per feature f); Px[n][t][f] written once, no atomics.
__global__ void k_gather_init(const float* __restrict__ x, int N) {
    int i = blockIdx.x * blockDim.x + threadIdx.x;
    int n = i >> 3;
    int f = i & 7;
    if (n >= N) return;
    float dn = g_dinv[n];
    float ns = g_nself[n];
    const float4* xs = (const float4*)(x + (size_t)n * 64 + f * 8);
    float4 sa = xs[0], sb = xs[1];
    float a0 = ns * sa.x, a1 = ns * sa.y, a2 = ns * sa.z, a3 = ns * sa.w;
    float a4 = ns * sb.x, a5 = ns * sb.y, a6 = ns * sb.z, a7 = ns * sb.w;
    int beg = g_off[n], end = g_off[n + 1];
#pragma unroll 4
    for (int j = beg; j < end; j++) {
        int s = g_csr[j];
        float ne = dn * g_dinv[s];
        const float4* xp = (const float4*)(x + (size_t)s * 64 + f * 8);
        float4 u = xp[0], v = xp[1];
        a0 = fmaf(u.x, ne, a0); a1 = fmaf(u.y, ne, a1);
        a2 = fmaf(u.z, ne, a2); a3 = fmaf(u.w, ne, a3);
        a4 = fmaf(v.x, ne, a4); a5 = fmaf(v.y, ne, a5);
        a6 = fmaf(v.z, ne, a6); a7 = fmaf(v.w, ne, a7);
    }
    float* pr = g_Px + (size_t)n * ROWF + f;   // Px[n][t][f] = pr[t*8]
    pr[0]  = a0; pr[8]  = a1; pr[16] = a2; pr[24] = a3;
    pr[32] = a4; pr[40] = a5; pr[48] = a6; pr[56] = a7;
}

// Gather-based propagation of h into one slot. Self term already stored by
// the scan epilogue (ps = nself*h), so accumulate on top of it.
__global__ void k_gather_h(int N, int slot) {
    int i = blockIdx.x * blockDim.x + threadIdx.x;
    int n = i >> 3;
    int f = i & 7;
    if (n >= N) return;
    float dn = g_dinv[n];
    float* pp = g_Px + (size_t)n * ROWF + slot * 8 + f;
    float acc = *pp;                       // self term from scan epilogue
    int beg = g_off[n], end = g_off[n + 1];
#pragma unroll 4
    for (int j = beg; j < end; j++) {
        int s = g_csr[j];
        float ne = dn * g_dinv[s];
        acc = fmaf(g_hbuf[(size_t)s * 8 + f], ne, acc);
    }
    *pp = acc;
}

__device__ __forceinline__ float sigmoid_f(float x) {
    return __fdividef(1.0f, 1.0f + __expf(-x));
}
__device__ __forceinline__ float tanh_f(float x) {
    float e = __expf(-2.0f * x);
    return __fdividef(1.0f - e, 1.0f + e);
}

// One 16B weight load feeds BOTH nodes (8 FMAs per LDS.128).
// Gate accumulators are fixed names cA0..cA3 / cB0..cB3.
#define ROWFMA2(BASE, ROW, VA, VB) do {                                   \
    float4 w_ = *(const float4*)((BASE) + (ROW) * 16 + q4);               \
    cA0 = fmaf((VA), w_.x, cA0); cA1 = fmaf((VA), w_.y, cA1);             \
    cA2 = fmaf((VA), w_.z, cA2); cA3 = fmaf((VA), w_.w, cA3);             \
    cB0 = fmaf((VB), w_.x, cB0); cB1 = fmaf((VB), w_.y, cB1);             \
    cB2 = fmaf((VB), w_.z, cB2); cB3 = fmaf((VB), w_.w, cB3); } while (0)

// Layer-1: 8 input features through an 8x16 weight, two nodes at once
#define DOT8P2(BASE) do {                                                 \
    ROWFMA2(BASE, 0, qaA.x, qaB.x);                                       \
    ROWFMA2(BASE, 1, qaA.y, qaB.y);                                       \
    ROWFMA2(BASE, 2, qaA.z, qaB.z);                                       \
    ROWFMA2(BASE, 3, qaA.w, qaB.w);                                       \
    ROWFMA2(BASE, 4, qbA.x, qbB.x);                                       \
    ROWFMA2(BASE, 5, qbA.y, qbB.y);                                       \
    ROWFMA2(BASE, 6, qbA.z, qbB.z);                                       \
    ROWFMA2(BASE, 7, qbA.w, qbB.w); } while (0)

// Gather 16 per-unit values spread 4-per-lane across the 4-lane node group
#define BCAST16(P, S0, S1, S2, S3) do {                                   \
    P##0  = __shfl_sync(0xffffffffu, S0, 0, 4);                           \
    P##1  = __shfl_sync(0xffffffffu, S1, 0, 4);                           \
    P##2  = __shfl_sync(0xffffffffu, S2, 0, 4);                           \
    P##3  = __shfl_sync(0xffffffffu, S3, 0, 4);                           \
    P##4  = __shfl_sync(0xffffffffu, S0, 1, 4);                           \
    P##5  = __shfl_sync(0xffffffffu, S1, 1, 4);                           \
    P##6  = __shfl_sync(0xffffffffu, S2, 1, 4);                           \
    P##7  = __shfl_sync(0xffffffffu, S3, 1, 4);                           \
    P##8  = __shfl_sync(0xffffffffu, S0, 2, 4);                           \
    P##9  = __shfl_sync(0xffffffffu, S1, 2, 4);                           \
    P##10 = __shfl_sync(0xffffffffu, S2, 2, 4);                           \
    P##11 = __shfl_sync(0xffffffffu, S3, 2, 4);                           \
    P##12 = __shfl_sync(0xffffffffu, S0, 3, 4);                           \
    P##13 = __shfl_sync(0xffffffffu, S1, 3, 4);                           \
    P##14 = __shfl_sync(0xffffffffu, S2, 3, 4);                           \
    P##15 = __shfl_sync(0xffffffffu, S3, 3, 4); } while (0)

// 16 broadcast values (per node) times rows [ROW0..ROW0+15], two nodes at once
#define DOT16_2(BASE, ROW0, PA, PB) do {                                  \
    ROWFMA2(BASE, (ROW0) + 0,  PA##0,  PB##0);                            \
    ROWFMA2(BASE, (ROW0) + 1,  PA##1,  PB##1);                            \
    ROWFMA2(BASE, (ROW0) + 2,  PA##2,  PB##2);                            \
    ROWFMA2(BASE, (ROW0) + 3,  PA##3,  PB##3);                            \
    ROWFMA2(BASE, (ROW0) + 4,  PA##4,  PB##4);                            \
    ROWFMA2(BASE, (ROW0) + 5,  PA##5,  PB##5);                            \
    ROWFMA2(BASE, (ROW0) + 6,  PA##6,  PB##6);                            \
    ROWFMA2(BASE, (ROW0) + 7,  PA##7,  PB##7);                            \
    ROWFMA2(BASE, (ROW0) + 8,  PA##8,  PB##8);                            \
    ROWFMA2(BASE, (ROW0) + 9,  PA##9,  PB##9);                            \
    ROWFMA2(BASE, (ROW0) + 10, PA##10, PB##10);                           \
    ROWFMA2(BASE, (ROW0) + 11, PA##11, PB##11);                           \
    ROWFMA2(BASE, (ROW0) + 12, PA##12, PB##12);                           \
    ROWFMA2(BASE, (ROW0) + 13, PA##13, PB##13);                           \
    ROWFMA2(BASE, (ROW0) + 14, PA##14, PB##14);                           \
    ROWFMA2(BASE, (ROW0) + 15, PA##15, PB##15); } while (0)

// Per-node output projection + stores (uses q, q4, sWo, sbo, out, o, N scope vars)
#define EPILOGUE(AX0, AX1, AX2, AX3, NODE, VALID) do {                    \
    float r0 = fmaxf(AX0, 0.f), r1 = fmaxf(AX1, 0.f);                     \
    float r2 = fmaxf(AX2, 0.f), r3 = fmaxf(AX3, 0.f);                     \
    float o0 = OUTF(0), o1 = OUTF(1), o2 = OUTF(2), o3 = OUTF(3);         \
    float o4 = OUTF(4), o5 = OUTF(5), o6 = OUTF(6), o7 = OUTF(7);         \
    o0 += __shfl_xor_sync(0xffffffffu, o0, 1, 4);                         \
    o1 += __shfl_xor_sync(0xffffffffu, o1, 1, 4);                         \
    o2 += __shfl_xor_sync(0xffffffffu, o2, 1, 4);                         \
    o3 += __shfl_xor_sync(0xffffffffu, o3, 1, 4);                         \
    o4 += __shfl_xor_sync(0xffffffffu, o4, 1, 4);                         \
    o5 += __shfl_xor_sync(0xffffffffu, o5, 1, 4);                         \
    o6 += __shfl_xor_sync(0xffffffffu, o6, 1, 4);                         \
    o7 += __shfl_xor_sync(0xffffffffu, o7, 1, 4);                         \
    o0 += __shfl_xor_sync(0xffffffffu, o0, 2, 4);                         \
    o1 += __shfl_xor_sync(0xffffffffu, o1, 2, 4);                         \
    o2 += __shfl_xor_sync(0xffffffffu, o2, 2, 4);                         \
    o3 += __shfl_xor_sync(0xffffffffu, o3, 2, 4);                         \
    o4 += __shfl_xor_sync(0xffffffffu, o4, 2, 4);                         \
    o5 += __shfl_xor_sync(0xffffffffu, o5, 2, 4);                         \
    o6 += __shfl_xor_sync(0xffffffffu, o6, 2, 4);                         \
    o7 += __shfl_xor_sync(0xffffffffu, o7, 2, 4);                         \
    o0 += sbo[0]; o1 += sbo[1]; o2 += sbo[2]; o3 += sbo[3];               \
    o4 += sbo[4]; o5 += sbo[5]; o6 += sbo[6]; o7 += sbo[7];               \
    float wa, wb2;                                                        \
    if      (q == 0) { wa = o0; wb2 = o1; }                               \
    else if (q == 1) { wa = o2; wb2 = o3; }                               \
    else if (q == 2) { wa = o4; wb2 = o5; }                               \
    else             { wa = o6; wb2 = o7; }                               \
    if (VALID) {                                                          \
        int f = 2 * q;                                                    \
        float* op = out + (size_t)(NODE) * 32 + o;                        \
        op[f * 4]       = wa;                                             \
        op[(f + 1) * 4] = wb2;                                            \
        if (o < 3) {                                                      \
            float ns = g_nself[(NODE)];                                   \
            float* hbp = g_hbuf + (size_t)(NODE) * 8;                     \
            float* psp = g_Px + (size_t)(NODE) * ROWF + (8 + o) * 8;      \
            hbp[f]     = wa;                                              \
            hbp[f + 1] = wb2;                                             \
            psp[f]     = ns * wa;                                         \
            psp[f + 1] = ns * wb2;                                        \
        }                                                                 \
    }                                                                     \
} while (0)

// Fused 8-step GRU scan for one output iteration o.
// 4 lanes per node, TWO nodes per lane (block covers 64 nodes).
__global__ void __launch_bounds__(128)
k_scan(const float* __restrict__ att,
       const float* __restrict__ Wz, const float* __restrict__ bz,
       const float* __restrict__ Lzw, const float* __restrict__ Lzb,
       const float* __restrict__ Wr, const float* __restrict__ br,
       const float* __restrict__ Lrw, const float* __restrict__ Lrb,
       const float* __restrict__ Wh, const float* __restrict__ bh,
       const float* __restrict__ Lhw, const float* __restrict__ Lhb,
       const float* __restrict__ Wout, const float* __restrict__ bout,
       float* __restrict__ out, int N, int o)
{
    __shared__ __align__(16) float sWz[128], sWr[128], sWh[128];
    __shared__ __align__(16) float sLz[512], sLr[512], sLh[512];
    __shared__ __align__(16) float sbz[16], sbr[16], sbh[16];
    __shared__ __align__(16) float sLzb[16], sLrb[16], sLhb[16];
    __shared__ __align__(16) float sWo[128], sbo[8], sp[8];

    int tid = threadIdx.x;
    if (tid < 128) { sWz[tid] = Wz[tid]; sWr[tid] = Wr[tid]; sWh[tid] = Wh[tid]; sWo[tid] = Wout[tid]; }
    for (int i = tid; i < 512; i += 128) { sLz[i] = Lzw[i]; sLr[i] = Lrw[i]; sLh[i] = Lhw[i]; }
    if (tid < 16) {
        sbz[tid] = bz[tid]; sbr[tid] = br[tid]; sbh[tid] = bh[tid];
        sLzb[tid] = Lzb[tid]; sLrb[tid] = Lrb[tid]; sLhb[tid] = Lhb[tid];
    }
    if (tid < 8) {
        sbo[tid] = bout[tid];
        // softmax(attention) with 8-lane butterflies — no arrays
        float v = att[tid];
        float m = v;
        m = fmaxf(m, __shfl_xor_sync(0xffu, m, 1, 8));
        m = fmaxf(m, __shfl_xor_sync(0xffu, m, 2, 8));
        m = fmaxf(m, __shfl_xor_sync(0xffu, m, 4, 8));
        float e = __expf(v - m);
        float s = e;
        s += __shfl_xor_sync(0xffu, s, 1, 8);
        s += __shfl_xor_sync(0xffu, s, 2, 8);
        s += __shfl_xor_sync(0xffu, s, 4, 8);
        sp[tid] = __fdividef(e, s);
    }
    __syncthreads();

    int g = tid >> 2;                       // lane group 0..31
    int nodeA = blockIdx.x * 64 + g;
    int nodeB = nodeA + 32;
    bool validA = (nodeA < N);
    bool validB = (nodeB < N);
    if (nodeA >= N) nodeA = N - 1;          // clamp, keep all lanes alive for shfl
    if (nodeB >= N) nodeB = N - 1;
    int q  = tid & 3;
    int q4 = q * 4;

    float HA0 = 0.f, HA1 = 0.f, HA2 = 0.f, HA3 = 0.f;
    float HB0 = 0.f, HB1 = 0.f, HB2 = 0.f, HB3 = 0.f;
    float AA0 = 0.f, AA1 = 0.f, AA2 = 0.f, AA3 = 0.f;
    float AB0 = 0.f, AB1 = 0.f, AB2 = 0.f, AB3 = 0.f;

    const float* prowA = g_Px + (size_t)nodeA * ROWF + o * 8;
    const float* prowB = g_Px + (size_t)nodeB * ROWF + o * 8;

#pragma unroll 1
    for (int t = 0; t < 8; t++) {
        float4 qaA = ((const float4*)(prowA + t * 8))[0];
        float4 qbA = ((const float4*)(prowA + t * 8))[1];
        float4 qaB = ((const float4*)(prowB + t * 8))[0];
        float4 qbB = ((const float4*)(prowB + t * 8))[1];

        float hbA0, hbA1, hbA2, hbA3, hbA4, hbA5, hbA6, hbA7,
              hbA8, hbA9, hbA10, hbA11, hbA12, hbA13, hbA14, hbA15;
        float hbB0, hbB1, hbB2, hbB3, hbB4, hbB5, hbB6, hbB7,
              hbB8, hbB9, hbB10, hbB11, hbB12, hbB13, hbB14, hbB15;
        float gbA0, gbA1, gbA2, gbA3, gbA4, gbA5, gbA6, gbA7,
              gbA8, gbA9, gbA10, gbA11, gbA12, gbA13, gbA14, gbA15;
        float gbB0, gbB1, gbB2, gbB3, gbB4, gbB5, gbB6, gbB7,
              gbB8, gbB9, gbB10, gbB11, gbB12, gbB13, gbB14, gbB15;
        BCAST16(hbA, HA0, HA1, HA2, HA3);
        BCAST16(hbB, HB0, HB1, HB2, HB3);

        float ZA0, ZA1, ZA2, ZA3, ZB0, ZB1, ZB2, ZB3;
        float RA0, RA1, RA2, RA3, RB0, RB1, RB2, RB3;
        float TA0, TA1, TA2, TA3, TB0, TB1, TB2, TB3;

        {   // ---- z gate ----
            float4 bv = *(const float4*)(sbz + q4);
            float cA0 = bv.x, cA1 = bv.y, cA2 = bv.z, cA3 = bv.w;
            float cB0 = bv.x, cB1 = bv.y, cB2 = bv.z, cB3 = bv.w;
            DOT8P2(sWz);
            BCAST16(gbA, cA0, cA1, cA2, cA3);
            BCAST16(gbB, cB0, cB1, cB2, cB3);
            bv = *(const float4*)(sLzb + q4);
            cA0 = bv.x; cA1 = bv.y; cA2 = bv.z; cA3 = bv.w;
            cB0 = bv.x; cB1 = bv.y; cB2 = bv.z; cB3 = bv.w;
            DOT16_2(sLz, 0,  gbA, gbB);
            DOT16_2(sLz, 16, hbA, hbB);
            ZA0 = sigmoid_f(cA0); ZA1 = sigmoid_f(cA1); ZA2 = sigmoid_f(cA2); ZA3 = sigmoid_f(cA3);
            ZB0 = sigmoid_f(cB0); ZB1 = sigmoid_f(cB1); ZB2 = sigmoid_f(cB2); ZB3 = sigmoid_f(cB3);
        }
        {   // ---- r gate -> H*R ----
            float4 bv = *(const float4*)(sbr + q4);
            float cA0 = bv.x, cA1 = bv.y, cA2 = bv.z, cA3 = bv.w;
            float cB0 = bv.x, cB1 = bv.y, cB2 = bv.z, cB3 = bv.w;
            DOT8P2(sWr);
            BCAST16(gbA, cA0, cA1, cA2, cA3);
            BCAST16(gbB, cB0, cB1, cB2, cB3);
            bv = *(const float4*)(sLrb + q4);
            cA0 = bv.x; cA1 = bv.y; cA2 = bv.z; cA3 = bv.w;
            cB0 = bv.x; cB1 = bv.y; cB2 = bv.z; cB3 = bv.w;
            DOT16_2(sLr, 0,  gbA, gbB);
            DOT16_2(sLr, 16, hbA, hbB);
            RA0 = HA0 * sigmoid_f(cA0); RA1 = HA1 * sigmoid_f(cA1);
            RA2 = HA2 * sigmoid_f(cA2); RA3 = HA3 * sigmoid_f(cA3);
            RB0 = HB0 * sigmoid_f(cB0); RB1 = HB1 * sigmoid_f(cB1);
            RB2 = HB2 * sigmoid_f(cB2); RB3 = HB3 * sigmoid_f(cB3);
        }
        {   // ---- h gate ----
            float4 bv = *(const float4*)(sbh + q4);
            float cA0 = bv.x, cA1 = bv.y, cA2 = bv.z, cA3 = bv.w;
            float cB0 = bv.x, cB1 = bv.y, cB2 = bv.z, cB3 = bv.w;
            DOT8P2(sWh);
            BCAST16(gbA, cA0, cA1, cA2, cA3);
            BCAST16(gbB, cB0, cB1, cB2, cB3);
            BCAST16(hbA, RA0, RA1, RA2, RA3);   // reuse hb regs for H*R broadcast
            BCAST16(hbB, RB0, RB1, RB2, RB3);
            bv = *(const float4*)(sLhb + q4);
            cA0 = bv.x; cA1 = bv.y; cA2 = bv.z; cA3 = bv.w;
            cB0 = bv.x; cB1 = bv.y; cB2 = bv.z; cB3 = bv.w;
            DOT16_2(sLh, 0,  gbA, gbB);
            DOT16_2(sLh, 16, hbA, hbB);
            TA0 = tanh_f(cA0); TA1 = tanh_f(cA1); TA2 = tanh_f(cA2); TA3 = tanh_f(cA3);
            TB0 = tanh_f(cB0); TB1 = tanh_f(cB1); TB2 = tanh_f(cB2); TB3 = tanh_f(cB3);
        }

        float pt = sp[t];
        HA0 = ZA0 * HA0 + (1.0f - ZA0) * TA0;  AA0 = fmaf(pt, HA0, AA0);
        HA1 = ZA1 * HA1 + (1.0f - ZA1) * TA1;  AA1 = fmaf(pt, HA1, AA1);
        HA2 = ZA2 * HA2 + (1.0f - ZA2) * TA2;  AA2 = fmaf(pt, HA2, AA2);
        HA3 = ZA3 * HA3 + (1.0f - ZA3) * TA3;  AA3 = fmaf(pt, HA3, AA3);
        HB0 = ZB0 * HB0 + (1.0f - ZB0) * TB0;  AB0 = fmaf(pt, HB0, AB0);
        HB1 = ZB1 * HB1 + (1.0f - ZB1) * TB1;  AB1 = fmaf(pt, HB1, AB1);
        HB2 = ZB2 * HB2 + (1.0f - ZB2) * TB2;  AB2 = fmaf(pt, HB2, AB2);
        HB3 = ZB3 * HB3 + (1.0f - ZB3) * TB3;  AB3 = fmaf(pt, HB3, AB3);
    }

#define OUTF(F) (fmaf(r0, sWo[(q4 + 0) * 8 + (F)],                        \
                 fmaf(r1, sWo[(q4 + 1) * 8 + (F)],                        \
                 fmaf(r2, sWo[(q4 + 2) * 8 + (F)],                        \
                      r3 * sWo[(q4 + 3) * 8 + (F)]))))
    EPILOGUE(AA0, AA1, AA2, AA3, nodeA, validA);
    EPILOGUE(AB0, AB1, AB2, AB3, nodeB, validB);
#undef OUTF
}

// ---------------------------------------------------------------------------
extern "C" void kernel_launch(void* const* d_in, const int* in_sizes, int n_in,
                              void* d_out, int out_size)
{
    const float* x    = (const float*)d_in[0];
    const int*   ei   = (const int*)d_in[1];
    const float* att  = (const float*)d_in[2];
    const float* Wz   = (const float*)d_in[3];
    const float* bz   = (const float*)d_in[4];
    const float* Lzw  = (const float*)d_in[5];
    const float* Lzb  = (const float*)d_in[6];
    const float* Wr   = (const float*)d_in[7];
    const float* br   = (const float*)d_in[8];
    const float* Lrw  = (const float*)d_in[9];
    const float* Lrb  = (const float*)d_in[10];
    const float* Wh   = (const float*)d_in[11];
    const float* bh   = (const float*)d_in[12];
    const float* Lhw  = (const float*)d_in[13];
    const float* Lhb  = (const float*)d_in[14];
    const float* Wout = (const float*)d_in[15];
    const float* bout = (const float*)d_in[16];
    float* out = (float*)d_out;

    int N = in_sizes[0] / (FND * TIN);
    int E = in_sizes[1] / 2;
    if (N > NN) N = NN;   // static scratch capacity guard
    if (E > EE) E = EE;

    const int TB = 256;
    // ---- CSR build (once per launch) ----
    k_zero_int<<<(N + TB - 1) / TB, TB>>>(N);
    k_cnt<<<(E + TB - 1) / TB, TB>>>(ei, E);
    k_norm<<<(N + TB - 1) / TB, TB>>>(N);
    k_prefix<<<1, 1024>>>(N);
    k_scatter<<<(E + TB - 1) / TB, TB>>>(ei, E);
    // ---- initial propagation (gather, no atomics) ----
    {
        long long tot = (long long)N * 8;
        k_gather_init<<<(int)((tot + TB - 1) / TB), TB>>>(x, N);
    }

    for (int o = 0; o < TOUTN; o++) {
        k_scan<<<(N + 63) / 64, 128>>>(att, Wz, bz, Lzw, Lzb, Wr, br, Lrw, Lrb,
                                       Wh, bh, Lhw, Lhb, Wout, bout, out, N, o);
        if (o < 3) {
            long long tot = (long long)N * 8;
            k_gather_h<<<(int)((tot + TB - 1) / TB), TB>>>(N, 8 + o);
        }
    }
}

// round 8
// speedup vs baseline: 1.7024x; 1.1204x over previous
#include <cuda_runtime.h>

// Problem constants (fixed by the dataset)
#define NN    50000
#define EE    800000
#define FND   8
#define TIN   8
#define HIDN  16
#define TOUTN 4
#define SLOTS 11   // 8 initial time slices + 3 propagated h's
#define ROWF  (SLOTS * FND)   // 88 floats per node row in g_Px

// Scratch (device globals: no allocation allowed)
__device__ int   g_cnt[NN];
__device__ int   g_pos[NN];
__device__ int   g_off[NN];
__device__ int   g_total;
__device__ int   g_csr[EE];              // src list grouped by dst
__device__ float g_dinv[NN];
__device__ float g_nself[NN];
__device__ float g_Px[(size_t)NN * ROWF];   // [n][slot][f], 17.6 MB
__device__ float g_hbuf[(size_t)NN * FND];

// ---------------------------------------------------------------------------
__global__ void k_zero_int(int N) {
    int i = blockIdx.x * blockDim.x + threadIdx.x;
    if (i < N) { g_cnt[i] = 0; g_pos[i] = 0; }
    if (i == 0) g_total = 0;
}

__global__ void k_cnt(const int* __restrict__ ei, int E) {
    int i = blockIdx.x * blockDim.x + threadIdx.x;
    if (i < E) atomicAdd(&g_cnt[ei[E + i]], 1);   // dst = ei[E + e]
}

__global__ void k_norm(int N) {
    int i = blockIdx.x * blockDim.x + threadIdx.x;
    if (i < N) {
        float d = (float)g_cnt[i] + 1.0f;
        g_dinv[i]  = rsqrtf(d);
        g_nself[i] = __fdividef(1.0f, d);   // dinv*dinv
    }
}

// Unordered CSR slot allocation: per-block scan + one global atomicAdd.
// Offsets are disjoint ranges; global ordering is irrelevant for the gather.
__global__ void k_alloc(int N) {
    __shared__ int wsum[8];
    __shared__ int sbase;
    int i = blockIdx.x * 256 + threadIdx.x;
    int lane = threadIdx.x & 31;
    int wid  = threadIdx.x >> 5;
    int c = (i < N) ? g_cnt[i] : 0;
    // inclusive warp scan of c
    int v = c;
#pragma unroll
    for (int d = 1; d < 32; d <<= 1) {
        int u = __shfl_up_sync(0xffffffffu, v, d);
        if (lane >= d) v += u;
    }
    if (lane == 31) wsum[wid] = v;
    __syncthreads();
    if (threadIdx.x < 8) {
        int w = wsum[threadIdx.x];
#pragma unroll
        for (int d = 1; d < 8; d <<= 1) {
            int u = __shfl_up_sync(0xffu, w, d, 8);
            if (threadIdx.x >= (unsigned)d) w += u;
        }
        wsum[threadIdx.x] = w;
        if (threadIdx.x == 7) sbase = atomicAdd(&g_total, w);
    }
    __syncthreads();
    int excl = v - c + (wid > 0 ? wsum[wid - 1] : 0) + sbase;
    if (i < N) g_off[i] = excl;
}

__global__ void k_scatter(const int* __restrict__ ei, int E) {
    int e = blockIdx.x * blockDim.x + threadIdx.x;
    if (e >= E) return;
    int d = ei[E + e];
    int p = atomicAdd(&g_pos[d], 1);
    g_csr[g_off[d] + p] = ei[e];
}

// Gather-based propagation of all 8 initial slices + self term.
// 8 threads per node (one per feature f); Px[n][t][f] written once, no atomics.
__global__ void k_gather_init(const float* __restrict__ x, int N) {
    int i = blockIdx.x * blockDim.x + threadIdx.x;
    int n = i >> 3;
    int f = i & 7;
    if (n >= N) return;
    float dn = g_dinv[n];
    float ns = g_nself[n];
    const float4* xs = (const float4*)(x + (size_t)n * 64 + f * 8);
    float4 sa = xs[0], sb = xs[1];
    float a0 = ns * sa.x, a1 = ns * sa.y, a2 = ns * sa.z, a3 = ns * sa.w;
    float a4 = ns * sb.x, a5 = ns * sb.y, a6 = ns * sb.z, a7 = ns * sb.w;
    int beg = g_off[n], end = beg + g_cnt[n];
#pragma unroll 4
    for (int j = beg; j < end; j++) {
        int s = g_csr[j];
        float ne = dn * g_dinv[s];
        const float4* xp = (const float4*)(x + (size_t)s * 64 + f * 8);
        float4 u = xp[0], v = xp[1];
        a0 = fmaf(u.x, ne, a0); a1 = fmaf(u.y, ne, a1);
        a2 = fmaf(u.z, ne, a2); a3 = fmaf(u.w, ne, a3);
        a4 = fmaf(v.x, ne, a4); a5 = fmaf(v.y, ne, a5);
        a6 = fmaf(v.z, ne, a6); a7 = fmaf(v.w, ne, a7);
    }
    float* pr = g_Px + (size_t)n * ROWF + f;   // Px[n][t][f] = pr[t*8]
    pr[0]  = a0; pr[8]  = a1; pr[16] = a2; pr[24] = a3;
    pr[32] = a4; pr[40] = a5; pr[48] = a6; pr[56] = a7;
}

// Gather-based propagation of h into one slot. Self term already stored by
// the scan epilogue (ps = nself*h), so accumulate on top of it.
__global__ void k_gather_h(int N, int slot) {
    int i = blockIdx.x * blockDim.x + threadIdx.x;
    int n = i >> 3;
    int f = i & 7;
    if (n >= N) return;
    float dn = g_dinv[n];
    float* pp = g_Px + (size_t)n * ROWF + slot * 8 + f;
    float acc = *pp;                       // self term from scan epilogue
    int beg = g_off[n], end = beg + g_cnt[n];
#pragma unroll 4
    for (int j = beg; j < end; j++) {
        int s = g_csr[j];
        float ne = dn * g_dinv[s];
        acc = fmaf(g_hbuf[(size_t)s * 8 + f], ne, acc);
    }
    *pp = acc;
}

__device__ __forceinline__ float sigmoid_f(float x) {
    return __fdividef(1.0f, 1.0f + __expf(-x));
}
__device__ __forceinline__ float tanh_f(float x) {
    float e = __expf(-2.0f * x);
    return __fdividef(1.0f - e, 1.0f + e);
}

// One 16B weight load feeds BOTH nodes (8 FMAs per LDS.128).
// Gate accumulators are fixed names cA0..cA3 / cB0..cB3.
#define ROWFMA2(BASE, ROW, VA, VB) do {                                   \
    float4 w_ = *(const float4*)((BASE) + (ROW) * 16 + q4);               \
    cA0 = fmaf((VA), w_.x, cA0); cA1 = fmaf((VA), w_.y, cA1);             \
    cA2 = fmaf((VA), w_.z, cA2); cA3 = fmaf((VA), w_.w, cA3);             \
    cB0 = fmaf((VB), w_.x, cB0); cB1 = fmaf((VB), w_.y, cB1);             \
    cB2 = fmaf((VB), w_.z, cB2); cB3 = fmaf((VB), w_.w, cB3); } while (0)

// Layer-1: 8 input features through an 8x16 weight, two nodes at once
#define DOT8P2(BASE) do {                                                 \
    ROWFMA2(BASE, 0, qaA.x, qaB.x);                                       \
    ROWFMA2(BASE, 1, qaA.y, qaB.y);                                       \
    ROWFMA2(BASE, 2, qaA.z, qaB.z);                                       \
    ROWFMA2(BASE, 3, qaA.w, qaB.w);                                       \
    ROWFMA2(BASE, 4, qbA.x, qbB.x);                                       \
    ROWFMA2(BASE, 5, qbA.y, qbB.y);                                       \
    ROWFMA2(BASE, 6, qbA.z, qbB.z);                                       \
    ROWFMA2(BASE, 7, qbA.w, qbB.w); } while (0)

// Gather 16 per-unit values spread 4-per-lane across the 4-lane node group
#define BCAST16(P, S0, S1, S2, S3) do {                                   \
    P##0  = __shfl_sync(0xffffffffu, S0, 0, 4);                           \
    P##1  = __shfl_sync(0xffffffffu, S1, 0, 4);                           \
    P##2  = __shfl_sync(0xffffffffu, S2, 0, 4);                           \
    P##3  = __shfl_sync(0xffffffffu, S3, 0, 4);                           \
    P##4  = __shfl_sync(0xffffffffu, S0, 1, 4);                           \
    P##5  = __shfl_sync(0xffffffffu, S1, 1, 4);                           \
    P##6  = __shfl_sync(0xffffffffu, S2, 1, 4);                           \
    P##7  = __shfl_sync(0xffffffffu, S3, 1, 4);                           \
    P##8  = __shfl_sync(0xffffffffu, S0, 2, 4);                           \
    P##9  = __shfl_sync(0xffffffffu, S1, 2, 4);                           \
    P##10 = __shfl_sync(0xffffffffu, S2, 2, 4);                           \
    P##11 = __shfl_sync(0xffffffffu, S3, 2, 4);                           \
    P##12 = __shfl_sync(0xffffffffu, S0, 3, 4);                           \
    P##13 = __shfl_sync(0xffffffffu, S1, 3, 4);                           \
    P##14 = __shfl_sync(0xffffffffu, S2, 3, 4);                           \
    P##15 = __shfl_sync(0xffffffffu, S3, 3, 4); } while (0)

// 16 broadcast values (per node) times rows [ROW0..ROW0+15], two nodes at once
#define DOT16_2(BASE, ROW0, PA, PB) do {                                  \
    ROWFMA2(BASE, (ROW0) + 0,  PA##0,  PB##0);                            \
    ROWFMA2(BASE, (ROW0) + 1,  PA##1,  PB##1);                            \
    ROWFMA2(BASE, (ROW0) + 2,  PA##2,  PB##2);                            \
    ROWFMA2(BASE, (ROW0) + 3,  PA##3,  PB##3);                            \
    ROWFMA2(BASE, (ROW0) + 4,  PA##4,  PB##4);                            \
    ROWFMA2(BASE, (ROW0) + 5,  PA##5,  PB##5);                            \
    ROWFMA2(BASE, (ROW0) + 6,  PA##6,  PB##6);                            \
    ROWFMA2(BASE, (ROW0) + 7,  PA##7,  PB##7);                            \
    ROWFMA2(BASE, (ROW0) + 8,  PA##8,  PB##8);                            \
    ROWFMA2(BASE, (ROW0) + 9,  PA##9,  PB##9);                            \
    ROWFMA2(BASE, (ROW0) + 10, PA##10, PB##10);                           \
    ROWFMA2(BASE, (ROW0) + 11, PA##11, PB##11);                           \
    ROWFMA2(BASE, (ROW0) + 12, PA##12, PB##12);                           \
    ROWFMA2(BASE, (ROW0) + 13, PA##13, PB##13);                           \
    ROWFMA2(BASE, (ROW0) + 14, PA##14, PB##14);                           \
    ROWFMA2(BASE, (ROW0) + 15, PA##15, PB##15); } while (0)

// Per-node output projection + stores (uses q, q4, sWo, sbo, out, o, N scope vars)
#define EPILOGUE(AX0, AX1, AX2, AX3, NODE, VALID) do {                    \
    float r0 = fmaxf(AX0, 0.f), r1 = fmaxf(AX1, 0.f);                     \
    float r2 = fmaxf(AX2, 0.f), r3 = fmaxf(AX3, 0.f);                     \
    float o0 = OUTF(0), o1 = OUTF(1), o2 = OUTF(2), o3 = OUTF(3);         \
    float o4 = OUTF(4), o5 = OUTF(5), o6 = OUTF(6), o7 = OUTF(7);         \
    o0 += __shfl_xor_sync(0xffffffffu, o0, 1, 4);                         \
    o1 += __shfl_xor_sync(0xffffffffu, o1, 1, 4);                         \
    o2 += __shfl_xor_sync(0xffffffffu, o2, 1, 4);                         \
    o3 += __shfl_xor_sync(0xffffffffu, o3, 1, 4);                         \
    o4 += __shfl_xor_sync(0xffffffffu, o4, 1, 4);                         \
    o5 += __shfl_xor_sync(0xffffffffu, o5, 1, 4);                         \
    o6 += __shfl_xor_sync(0xffffffffu, o6, 1, 4);                         \
    o7 += __shfl_xor_sync(0xffffffffu, o7, 1, 4);                         \
    o0 += __shfl_xor_sync(0xffffffffu, o0, 2, 4);                         \
    o1 += __shfl_xor_sync(0xffffffffu, o1, 2, 4);                         \
    o2 += __shfl_xor_sync(0xffffffffu, o2, 2, 4);                         \
    o3 += __shfl_xor_sync(0xffffffffu, o3, 2, 4);                         \
    o4 += __shfl_xor_sync(0xffffffffu, o4, 2, 4);                         \
    o5 += __shfl_xor_sync(0xffffffffu, o5, 2, 4);                         \
    o6 += __shfl_xor_sync(0xffffffffu, o6, 2, 4);                         \
    o7 += __shfl_xor_sync(0xffffffffu, o7, 2, 4);                         \
    o0 += sbo[0]; o1 += sbo[1]; o2 += sbo[2]; o3 += sbo[3];               \
    o4 += sbo[4]; o5 += sbo[5]; o6 += sbo[6]; o7 += sbo[7];               \
    float wa, wb2;                                                        \
    if      (q == 0) { wa = o0; wb2 = o1; }                               \
    else if (q == 1) { wa = o2; wb2 = o3; }                               \
    else if (q == 2) { wa = o4; wb2 = o5; }                               \
    else             { wa = o6; wb2 = o7; }                               \
    if (VALID) {                                                          \
        int f = 2 * q;                                                    \
        float* op = out + (size_t)(NODE) * 32 + o;                        \
        op[f * 4]       = wa;                                             \
        op[(f + 1) * 4] = wb2;                                            \
        if (o < 3) {                                                      \
            float ns = g_nself[(NODE)];                                   \
            float* hbp = g_hbuf + (size_t)(NODE) * 8;                     \
            float* psp = g_Px + (size_t)(NODE) * ROWF + (8 + o) * 8;      \
            hbp[f]     = wa;                                              \
            hbp[f + 1] = wb2;                                             \
            psp[f]     = ns * wa;                                         \
            psp[f + 1] = ns * wb2;                                        \
        }                                                                 \
    }                                                                     \
} while (0)

// Fused 8-step GRU scan for one output iteration o.
// 4 lanes per node, TWO nodes per lane (block covers 64 nodes).
__global__ void __launch_bounds__(128)
k_scan(const float* __restrict__ att,
       const float* __restrict__ Wz, const float* __restrict__ bz,
       const float* __restrict__ Lzw, const float* __restrict__ Lzb,
       const float* __restrict__ Wr, const float* __restrict__ br,
       const float* __restrict__ Lrw, const float* __restrict__ Lrb,
       const float* __restrict__ Wh, const float* __restrict__ bh,
       const float* __restrict__ Lhw, const float* __restrict__ Lhb,
       const float* __restrict__ Wout, const float* __restrict__ bout,
       float* __restrict__ out, int N, int o)
{
    __shared__ __align__(16) float sWz[128], sWr[128], sWh[128];
    __shared__ __align__(16) float sLz[512], sLr[512], sLh[512];
    __shared__ __align__(16) float sbz[16], sbr[16], sbh[16];
    __shared__ __align__(16) float sLzb[16], sLrb[16], sLhb[16];
    __shared__ __align__(16) float sWo[128], sbo[8], sp[8];

    int tid = threadIdx.x;
    if (tid < 128) { sWz[tid] = Wz[tid]; sWr[tid] = Wr[tid]; sWh[tid] = Wh[tid]; sWo[tid] = Wout[tid]; }
    for (int i = tid; i < 512; i += 128) { sLz[i] = Lzw[i]; sLr[i] = Lrw[i]; sLh[i] = Lhw[i]; }
    if (tid < 16) {
        sbz[tid] = bz[tid]; sbr[tid] = br[tid]; sbh[tid] = bh[tid];
        sLzb[tid] = Lzb[tid]; sLrb[tid] = Lrb[tid]; sLhb[tid] = Lhb[tid];
    }
    if (tid < 8) {
        sbo[tid] = bout[tid];
        // softmax(attention) with 8-lane butterflies — no arrays
        float v = att[tid];
        float m = v;
        m = fmaxf(m, __shfl_xor_sync(0xffu, m, 1, 8));
        m = fmaxf(m, __shfl_xor_sync(0xffu, m, 2, 8));
        m = fmaxf(m, __shfl_xor_sync(0xffu, m, 4, 8));
        float e = __expf(v - m);
        float s = e;
        s += __shfl_xor_sync(0xffu, s, 1, 8);
        s += __shfl_xor_sync(0xffu, s, 2, 8);
        s += __shfl_xor_sync(0xffu, s, 4, 8);
        sp[tid] = __fdividef(e, s);
    }
    __syncthreads();

    int g = tid >> 2;                       // lane group 0..31
    int nodeA = blockIdx.x * 64 + g;
    int nodeB = nodeA + 32;
    bool validA = (nodeA < N);
    bool validB = (nodeB < N);
    if (nodeA >= N) nodeA = N - 1;          // clamp, keep all lanes alive for shfl
    if (nodeB >= N) nodeB = N - 1;
    int q  = tid & 3;
    int q4 = q * 4;

    float HA0 = 0.f, HA1 = 0.f, HA2 = 0.f, HA3 = 0.f;
    float HB0 = 0.f, HB1 = 0.f, HB2 = 0.f, HB3 = 0.f;
    float AA0 = 0.f, AA1 = 0.f, AA2 = 0.f, AA3 = 0.f;
    float AB0 = 0.f, AB1 = 0.f, AB2 = 0.f, AB3 = 0.f;

    const float* prowA = g_Px + (size_t)nodeA * ROWF + o * 8;
    const float* prowB = g_Px + (size_t)nodeB * ROWF + o * 8;

#pragma unroll 1
    for (int t = 0; t < 8; t++) {
        float4 qaA = ((const float4*)(prowA + t * 8))[0];
        float4 qbA = ((const float4*)(prowA + t * 8))[1];
        float4 qaB = ((const float4*)(prowB + t * 8))[0];
        float4 qbB = ((const float4*)(prowB + t * 8))[1];

        float hbA0, hbA1, hbA2, hbA3, hbA4, hbA5, hbA6, hbA7,
              hbA8, hbA9, hbA10, hbA11, hbA12, hbA13, hbA14, hbA15;
        float hbB0, hbB1, hbB2, hbB3, hbB4, hbB5, hbB6, hbB7,
              hbB8, hbB9, hbB10, hbB11, hbB12, hbB13, hbB14, hbB15;
        float gbA0, gbA1, gbA2, gbA3, gbA4, gbA5, gbA6, gbA7,
              gbA8, gbA9, gbA10, gbA11, gbA12, gbA13, gbA14, gbA15;
        float gbB0, gbB1, gbB2, gbB3, gbB4, gbB5, gbB6, gbB7,
              gbB8, gbB9, gbB10, gbB11, gbB12, gbB13, gbB14, gbB15;
        BCAST16(hbA, HA0, HA1, HA2, HA3);
        BCAST16(hbB, HB0, HB1, HB2, HB3);

        float ZA0, ZA1, ZA2, ZA3, ZB0, ZB1, ZB2, ZB3;
        float RA0, RA1, RA2, RA3, RB0, RB1, RB2, RB3;
        float TA0, TA1, TA2, TA3, TB0, TB1, TB2, TB3;

        {   // ---- z gate ----
            float4 bv = *(const float4*)(sbz + q4);
            float cA0 = bv.x, cA1 = bv.y, cA2 = bv.z, cA3 = bv.w;
            float cB0 = bv.x, cB1 = bv.y, cB2 = bv.z, cB3 = bv.w;
            DOT8P2(sWz);
            BCAST16(gbA, cA0, cA1, cA2, cA3);
            BCAST16(gbB, cB0, cB1, cB2, cB3);
            bv = *(const float4*)(sLzb + q4);
            cA0 = bv.x; cA1 = bv.y; cA2 = bv.z; cA3 = bv.w;
            cB0 = bv.x; cB1 = bv.y; cB2 = bv.z; cB3 = bv.w;
            DOT16_2(sLz, 0,  gbA, gbB);
            DOT16_2(sLz, 16, hbA, hbB);
            ZA0 = sigmoid_f(cA0); ZA1 = sigmoid_f(cA1); ZA2 = sigmoid_f(cA2); ZA3 = sigmoid_f(cA3);
            ZB0 = sigmoid_f(cB0); ZB1 = sigmoid_f(cB1); ZB2 = sigmoid_f(cB2); ZB3 = sigmoid_f(cB3);
        }
        {   // ---- r gate -> H*R ----
            float4 bv = *(const float4*)(sbr + q4);
            float cA0 = bv.x, cA1 = bv.y, cA2 = bv.z, cA3 = bv.w;
            float cB0 = bv.x, cB1 = bv.y, cB2 = bv.z, cB3 = bv.w;
            DOT8P2(sWr);
            BCAST16(gbA, cA0, cA1, cA2, cA3);
            BCAST16(gbB, cB0, cB1, cB2, cB3);
            bv = *(const float4*)(sLrb + q4);
            cA0 = bv.x; cA1 = bv.y; cA2 = bv.z; cA3 = bv.w;
            cB0 = bv.x; cB1 = bv.y; cB2 = bv.z; cB3 = bv.w;
            DOT16_2(sLr, 0,  gbA, gbB);
            DOT16_2(sLr, 16, hbA, hbB);
            RA0 = HA0 * sigmoid_f(cA0); RA1 = HA1 * sigmoid_f(cA1);
            RA2 = HA2 * sigmoid_f(cA2); RA3 = HA3 * sigmoid_f(cA3);
            RB0 = HB0 * sigmoid_f(cB0); RB1 = HB1 * sigmoid_f(cB1);
            RB2 = HB2 * sigmoid_f(cB2); RB3 = HB3 * sigmoid_f(cB3);
        }
        {   // ---- h gate ----
            float4 bv = *(const float4*)(sbh + q4);
            float cA0 = bv.x, cA1 = bv.y, cA2 = bv.z, cA3 = bv.w;
            float cB0 = bv.x, cB1 = bv.y, cB2 = bv.z, cB3 = bv.w;
            DOT8P2(sWh);
            BCAST16(gbA, cA0, cA1, cA2, cA3);
            BCAST16(gbB, cB0, cB1, cB2, cB3);
            BCAST16(hbA, RA0, RA1, RA2, RA3);   // reuse hb regs for H*R broadcast
            BCAST16(hbB, RB0, RB1, RB2, RB3);
            bv = *(const float4*)(sLhb + q4);
            cA0 = bv.x; cA1 = bv.y; cA2 = bv.z; cA3 = bv.w;
            cB0 = bv.x; cB1 = bv.y; cB2 = bv.z; cB3 = bv.w;
            DOT16_2(sLh, 0,  gbA, gbB);
            DOT16_2(sLh, 16, hbA, hbB);
            TA0 = tanh_f(cA0); TA1 = tanh_f(cA1); TA2 = tanh_f(cA2); TA3 = tanh_f(cA3);
            TB0 = tanh_f(cB0); TB1 = tanh_f(cB1); TB2 = tanh_f(cB2); TB3 = tanh_f(cB3);
        }

        float pt = sp[t];
        HA0 = ZA0 * HA0 + (1.0f - ZA0) * TA0;  AA0 = fmaf(pt, HA0, AA0);
        HA1 = ZA1 * HA1 + (1.0f - ZA1) * TA1;  AA1 = fmaf(pt, HA1, AA1);
        HA2 = ZA2 * HA2 + (1.0f - ZA2) * TA2;  AA2 = fmaf(pt, HA2, AA2);
        HA3 = ZA3 * HA3 + (1.0f - ZA3) * TA3;  AA3 = fmaf(pt, HA3, AA3);
        HB0 = ZB0 * HB0 + (1.0f - ZB0) * TB0;  AB0 = fmaf(pt, HB0, AB0);
        HB1 = ZB1 * HB1 + (1.0f - ZB1) * TB1;  AB1 = fmaf(pt, HB1, AB1);
        HB2 = ZB2 * HB2 + (1.0f - ZB2) * TB2;  AB2 = fmaf(pt, HB2, AB2);
        HB3 = ZB3 * HB3 + (1.0f - ZB3) * TB3;  AB3 = fmaf(pt, HB3, AB3);
    }

#define OUTF(F) (fmaf(r0, sWo[(q4 + 0) * 8 + (F)],                        \
                 fmaf(r1, sWo[(q4 + 1) * 8 + (F)],                        \
                 fmaf(r2, sWo[(q4 + 2) * 8 + (F)],                        \
                      r3 * sWo[(q4 + 3) * 8 + (F)]))))
    EPILOGUE(AA0, AA1, AA2, AA3, nodeA, validA);
    EPILOGUE(AB0, AB1, AB2, AB3, nodeB, validB);
#undef OUTF
}

// ---------------------------------------------------------------------------
extern "C" void kernel_launch(void* const* d_in, const int* in_sizes, int n_in,
                              void* d_out, int out_size)
{
    const float* x    = (const float*)d_in[0];
    const int*   ei   = (const int*)d_in[1];
    const float* att  = (const float*)d_in[2];
    const float* Wz   = (const float*)d_in[3];
    const float* bz   = (const float*)d_in[4];
    const float* Lzw  = (const float*)d_in[5];
    const float* Lzb  = (const float*)d_in[6];
    const float* Wr   = (const float*)d_in[7];
    const float* br   = (const float*)d_in[8];
    const float* Lrw  = (const float*)d_in[9];
    const float* Lrb  = (const float*)d_in[10];
    const float* Wh   = (const float*)d_in[11];
    const float* bh   = (const float*)d_in[12];
    const float* Lhw  = (const float*)d_in[13];
    const float* Lhb  = (const float*)d_in[14];
    const float* Wout = (const float*)d_in[15];
    const float* bout = (const float*)d_in[16];
    float* out = (float*)d_out;

    int N = in_sizes[0] / (FND * TIN);
    int E = in_sizes[1] / 2;
    if (N > NN) N = NN;   // static scratch capacity guard
    if (E > EE) E = EE;

    const int TB = 256;
    // ---- CSR build (once per launch) ----
    k_zero_int<<<(N + TB - 1) / TB, TB>>>(N);
    k_cnt<<<(E + TB - 1) / TB, TB>>>(ei, E);
    k_norm<<<(N + TB - 1) / TB, TB>>>(N);
    k_alloc<<<(N + 255) / 256, 256>>>(N);
    k_scatter<<<(E + TB - 1) / TB, TB>>>(ei, E);
    // ---- initial propagation (gather, no atomics) ----
    {
        long long tot = (long long)N * 8;
        k_gather_init<<<(int)((tot + TB - 1) / TB), TB>>>(x, N);
    }

    for (int o = 0; o < TOUTN; o++) {
        k_scan<<<(N + 63) / 64, 128>>>(att, Wz, bz, Lzw, Lzb, Wr, br, Lrw, Lrb,
                                       Wh, bh, Lhw, Lhb, Wout, bout, out, N, o);
        if (o < 3) {
            long long tot = (long long)N * 8;
            k_gather_h<<<(int)((tot + TB - 1) / TB), TB>>>(N, 8 + o);
        }
    }
}

// round 9
// speedup vs baseline: 2.4325x; 1.4289x over previous
#include <cuda_runtime.h>

// Problem constants (fixed by the dataset)
#define NN    50000
#define EE    800000
#define FND   8
#define TIN   8
#define HIDN  16
#define TOUTN 4
#define SLOTS 11   // 8 initial time slices + 3 propagated h's
#define ROWF  (SLOTS * FND)   // 88 floats per node row in g_Px

// Scratch (device globals: no allocation allowed)
__device__ int   g_cnt[NN];
__device__ int   g_pos[NN];
__device__ int   g_off[NN];
__device__ int   g_total;
__device__ int   g_csr[EE];              // src list grouped by dst
__device__ float g_dinv[NN];
__device__ float g_nself[NN];
__device__ float g_Px[(size_t)NN * ROWF];   // [n][slot][f], 17.6 MB
__device__ float g_hbuf[(size_t)NN * FND];
__device__ float g_M[3 * 128];           // folded W@L_top per gate (8x16)
__device__ float g_fb[3 * 16];           // folded bias b@L_top + Lb per gate

// ---------------------------------------------------------------------------
__global__ void k_zero_int(int N) {
    int i = blockIdx.x * blockDim.x + threadIdx.x;
    if (i < N) { g_cnt[i] = 0; g_pos[i] = 0; }
    if (i == 0) g_total = 0;
}

__global__ void k_cnt(const int* __restrict__ ei, int E) {
    int i = blockIdx.x * blockDim.x + threadIdx.x;
    if (i < E) atomicAdd(&g_cnt[ei[E + i]], 1);   // dst = ei[E + e]
}

__global__ void k_norm(int N) {
    int i = blockIdx.x * blockDim.x + threadIdx.x;
    if (i < N) {
        float d = (float)g_cnt[i] + 1.0f;
        g_dinv[i]  = rsqrtf(d);
        g_nself[i] = __fdividef(1.0f, d);   // dinv*dinv
    }
}

// Fold the two-layer gate algebra:
//   concat(P@W + b, H) @ L + Lb  ==  P@(W@L_top) + (b@L_top + Lb) + H@L_bot
// Precompute M = W@L_top (8x16) and fb = b@L_top + Lb (16) for each gate.
// 48 threads: gate = t/16 (z,r,h), col j = t%16.
__global__ void k_fold(const float* __restrict__ Wz, const float* __restrict__ bz,
                       const float* __restrict__ Lzw, const float* __restrict__ Lzb,
                       const float* __restrict__ Wr, const float* __restrict__ br,
                       const float* __restrict__ Lrw, const float* __restrict__ Lrb,
                       const float* __restrict__ Wh, const float* __restrict__ bh,
                       const float* __restrict__ Lhw, const float* __restrict__ Lhb) {
    int t = threadIdx.x;
    if (t >= 48) return;
    int gate = t >> 4;
    int j = t & 15;
    const float *W, *b, *L, *Lb;
    if      (gate == 0) { W = Wz; b = bz; L = Lzw; Lb = Lzb; }
    else if (gate == 1) { W = Wr; b = br; L = Lrw; Lb = Lrb; }
    else                { W = Wh; b = bh; L = Lhw; Lb = Lhb; }
#pragma unroll
    for (int k = 0; k < 8; k++) {
        float m = 0.0f;
#pragma unroll
        for (int i = 0; i < 16; i++) m = fmaf(W[k * 16 + i], L[i * 16 + j], m);
        g_M[gate * 128 + k * 16 + j] = m;
    }
    float fb = Lb[j];
#pragma unroll
    for (int i = 0; i < 16; i++) fb = fmaf(b[i], L[i * 16 + j], fb);
    g_fb[gate * 16 + j] = fb;
}

// Unordered CSR slot allocation: per-block scan + one global atomicAdd.
// Offsets are disjoint ranges; global ordering is irrelevant for the gather.
__global__ void k_alloc(int N) {
    __shared__ int wsum[8];
    __shared__ int sbase;
    int i = blockIdx.x * 256 + threadIdx.x;
    int lane = threadIdx.x & 31;
    int wid  = threadIdx.x >> 5;
    int c = (i < N) ? g_cnt[i] : 0;
    int v = c;
#pragma unroll
    for (int d = 1; d < 32; d <<= 1) {
        int u = __shfl_up_sync(0xffffffffu, v, d);
        if (lane >= d) v += u;
    }
    if (lane == 31) wsum[wid] = v;
    __syncthreads();
    if (threadIdx.x < 8) {
        int w = wsum[threadIdx.x];
#pragma unroll
        for (int d = 1; d < 8; d <<= 1) {
            int u = __shfl_up_sync(0xffu, w, d, 8);
            if (threadIdx.x >= (unsigned)d) w += u;
        }
        wsum[threadIdx.x] = w;
        if (threadIdx.x == 7) sbase = atomicAdd(&g_total, w);
    }
    __syncthreads();
    int excl = v - c + (wid > 0 ? wsum[wid - 1] : 0) + sbase;
    if (i < N) g_off[i] = excl;
}

__global__ void k_scatter(const int* __restrict__ ei, int E) {
    int e = blockIdx.x * blockDim.x + threadIdx.x;
    if (e >= E) return;
    int d = ei[E + e];
    int p = atomicAdd(&g_pos[d], 1);
    g_csr[g_off[d] + p] = ei[e];
}

// Gather-based propagation of all 8 initial slices + self term.
__global__ void k_gather_init(const float* __restrict__ x, int N) {
    int i = blockIdx.x * blockDim.x + threadIdx.x;
    int n = i >> 3;
    int f = i & 7;
    if (n >= N) return;
    float dn = g_dinv[n];
    float ns = g_nself[n];
    const float4* xs = (const float4*)(x + (size_t)n * 64 + f * 8);
    float4 sa = xs[0], sb = xs[1];
    float a0 = ns * sa.x, a1 = ns * sa.y, a2 = ns * sa.z, a3 = ns * sa.w;
    float a4 = ns * sb.x, a5 = ns * sb.y, a6 = ns * sb.z, a7 = ns * sb.w;
    int beg = g_off[n], end = beg + g_cnt[n];
#pragma unroll 4
    for (int j = beg; j < end; j++) {
        int s = g_csr[j];
        float ne = dn * g_dinv[s];
        const float4* xp = (const float4*)(x + (size_t)s * 64 + f * 8);
        float4 u = xp[0], v = xp[1];
        a0 = fmaf(u.x, ne, a0); a1 = fmaf(u.y, ne, a1);
        a2 = fmaf(u.z, ne, a2); a3 = fmaf(u.w, ne, a3);
        a4 = fmaf(v.x, ne, a4); a5 = fmaf(v.y, ne, a5);
        a6 = fmaf(v.z, ne, a6); a7 = fmaf(v.w, ne, a7);
    }
    float* pr = g_Px + (size_t)n * ROWF + f;   // Px[n][t][f] = pr[t*8]
    pr[0]  = a0; pr[8]  = a1; pr[16] = a2; pr[24] = a3;
    pr[32] = a4; pr[40] = a5; pr[48] = a6; pr[56] = a7;
}

// Gather-based propagation of h into one slot (self term pre-stored by scan).
__global__ void k_gather_h(int N, int slot) {
    int i = blockIdx.x * blockDim.x + threadIdx.x;
    int n = i >> 3;
    int f = i & 7;
    if (n >= N) return;
    float dn = g_dinv[n];
    float* pp = g_Px + (size_t)n * ROWF + slot * 8 + f;
    float acc = *pp;
    int beg = g_off[n], end = beg + g_cnt[n];
#pragma unroll 4
    for (int j = beg; j < end; j++) {
        int s = g_csr[j];
        float ne = dn * g_dinv[s];
        acc = fmaf(g_hbuf[(size_t)s * 8 + f], ne, acc);
    }
    *pp = acc;
}

__device__ __forceinline__ float sigmoid_f(float x) {
    return __fdividef(1.0f, 1.0f + __expf(-x));
}
__device__ __forceinline__ float tanh_f(float x) {
    float e = __expf(-2.0f * x);
    return __fdividef(1.0f - e, 1.0f + e);
}

// One 16B weight load feeds BOTH nodes (8 FMAs per LDS.128).
#define ROWFMA2(BASE, ROW, VA, VB) do {                                   \
    float4 w_ = *(const float4*)((BASE) + (ROW) * 16 + q4);               \
    cA0 = fmaf((VA), w_.x, cA0); cA1 = fmaf((VA), w_.y, cA1);             \
    cA2 = fmaf((VA), w_.z, cA2); cA3 = fmaf((VA), w_.w, cA3);             \
    cB0 = fmaf((VB), w_.x, cB0); cB1 = fmaf((VB), w_.y, cB1);             \
    cB2 = fmaf((VB), w_.z, cB2); cB3 = fmaf((VB), w_.w, cB3); } while (0)

// Layer-1 folded: 8 input features through the 8x16 M matrix, two nodes at once
#define DOT8P2(BASE) do {                                                 \
    ROWFMA2(BASE, 0, qaA.x, qaB.x);                                       \
    ROWFMA2(BASE, 1, qaA.y, qaB.y);                                       \
    ROWFMA2(BASE, 2, qaA.z, qaB.z);                                       \
    ROWFMA2(BASE, 3, qaA.w, qaB.w);                                       \
    ROWFMA2(BASE, 4, qbA.x, qbB.x);                                       \
    ROWFMA2(BASE, 5, qbA.y, qbB.y);                                       \
    ROWFMA2(BASE, 6, qbA.z, qbB.z);                                       \
    ROWFMA2(BASE, 7, qbA.w, qbB.w); } while (0)

// Gather 16 per-unit values spread 4-per-lane across the 4-lane node group
#define BCAST16(P, S0, S1, S2, S3) do {                                   \
    P##0  = __shfl_sync(0xffffffffu, S0, 0, 4);                           \
    P##1  = __shfl_sync(0xffffffffu, S1, 0, 4);                           \
    P##2  = __shfl_sync(0xffffffffu, S2, 0, 4);                           \
    P##3  = __shfl_sync(0xffffffffu, S3, 0, 4);                           \
    P##4  = __shfl_sync(0xffffffffu, S0, 1, 4);                           \
    P##5  = __shfl_sync(0xffffffffu, S1, 1, 4);                           \
    P##6  = __shfl_sync(0xffffffffu, S2, 1, 4);                           \
    P##7  = __shfl_sync(0xffffffffu, S3, 1, 4);                           \
    P##8  = __shfl_sync(0xffffffffu, S0, 2, 4);                           \
    P##9  = __shfl_sync(0xffffffffu, S1, 2, 4);                           \
    P##10 = __shfl_sync(0xffffffffu, S2, 2, 4);                           \
    P##11 = __shfl_sync(0xffffffffu, S3, 2, 4);                           \
    P##12 = __shfl_sync(0xffffffffu, S0, 3, 4);                           \
    P##13 = __shfl_sync(0xffffffffu, S1, 3, 4);                           \
    P##14 = __shfl_sync(0xffffffffu, S2, 3, 4);                           \
    P##15 = __shfl_sync(0xffffffffu, S3, 3, 4); } while (0)

// 16 broadcast values (per node) times 16 rows of the H-portion matrix
#define DOT16H(BASE, PA, PB) do {                                         \
    ROWFMA2(BASE, 0,  PA##0,  PB##0);                                     \
    ROWFMA2(BASE, 1,  PA##1,  PB##1);                                     \
    ROWFMA2(BASE, 2,  PA##2,  PB##2);                                     \
    ROWFMA2(BASE, 3,  PA##3,  PB##3);                                     \
    ROWFMA2(BASE, 4,  PA##4,  PB##4);                                     \
    ROWFMA2(BASE, 5,  PA##5,  PB##5);                                     \
    ROWFMA2(BASE, 6,  PA##6,  PB##6);                                     \
    ROWFMA2(BASE, 7,  PA##7,  PB##7);                                     \
    ROWFMA2(BASE, 8,  PA##8,  PB##8);                                     \
    ROWFMA2(BASE, 9,  PA##9,  PB##9);                                     \
    ROWFMA2(BASE, 10, PA##10, PB##10);                                    \
    ROWFMA2(BASE, 11, PA##11, PB##11);                                    \
    ROWFMA2(BASE, 12, PA##12, PB##12);                                    \
    ROWFMA2(BASE, 13, PA##13, PB##13);                                    \
    ROWFMA2(BASE, 14, PA##14, PB##14);                                    \
    ROWFMA2(BASE, 15, PA##15, PB##15); } while (0)

// Per-node output projection + stores
#define EPILOGUE(AX0, AX1, AX2, AX3, NODE, VALID) do {                    \
    float r0 = fmaxf(AX0, 0.f), r1 = fmaxf(AX1, 0.f);                     \
    float r2 = fmaxf(AX2, 0.f), r3 = fmaxf(AX3, 0.f);                     \
    float o0 = OUTF(0), o1 = OUTF(1), o2 = OUTF(2), o3 = OUTF(3);         \
    float o4 = OUTF(4), o5 = OUTF(5), o6 = OUTF(6), o7 = OUTF(7);         \
    o0 += __shfl_xor_sync(0xffffffffu, o0, 1, 4);                         \
    o1 += __shfl_xor_sync(0xffffffffu, o1, 1, 4);                         \
    o2 += __shfl_xor_sync(0xffffffffu, o2, 1, 4);                         \
    o3 += __shfl_xor_sync(0xffffffffu, o3, 1, 4);                         \
    o4 += __shfl_xor_sync(0xffffffffu, o4, 1, 4);                         \
    o5 += __shfl_xor_sync(0xffffffffu, o5, 1, 4);                         \
    o6 += __shfl_xor_sync(0xffffffffu, o6, 1, 4);                         \
    o7 += __shfl_xor_sync(0xffffffffu, o7, 1, 4);                         \
    o0 += __shfl_xor_sync(0xffffffffu, o0, 2, 4);                         \
    o1 += __shfl_xor_sync(0xffffffffu, o1, 2, 4);                         \
    o2 += __shfl_xor_sync(0xffffffffu, o2, 2, 4);                         \
    o3 += __shfl_xor_sync(0xffffffffu, o3, 2, 4);                         \
    o4 += __shfl_xor_sync(0xffffffffu, o4, 2, 4);                         \
    o5 += __shfl_xor_sync(0xffffffffu, o5, 2, 4);                         \
    o6 += __shfl_xor_sync(0xffffffffu, o6, 2, 4);                         \
    o7 += __shfl_xor_sync(0xffffffffu, o7, 2, 4);                         \
    o0 += sbo[0]; o1 += sbo[1]; o2 += sbo[2]; o3 += sbo[3];               \
    o4 += sbo[4]; o5 += sbo[5]; o6 += sbo[6]; o7 += sbo[7];               \
    float wa, wb2;                                                        \
    if      (q == 0) { wa = o0; wb2 = o1; }                               \
    else if (q == 1) { wa = o2; wb2 = o3; }                               \
    else if (q == 2) { wa = o4; wb2 = o5; }                               \
    else             { wa = o6; wb2 = o7; }                               \
    if (VALID) {                                                          \
        int f = 2 * q;                                                    \
        float* op = out + (size_t)(NODE) * 32 + o;                        \
        op[f * 4]       = wa;                                             \
        op[(f + 1) * 4] = wb2;                                            \
        if (o < 3) {                                                      \
            float ns = g_nself[(NODE)];                                   \
            float* hbp = g_hbuf + (size_t)(NODE) * 8;                     \
            float* psp = g_Px + (size_t)(NODE) * ROWF + (8 + o) * 8;      \
            hbp[f]     = wa;                                              \
            hbp[f + 1] = wb2;                                             \
            psp[f]     = ns * wa;                                         \
            psp[f + 1] = ns * wb2;                                        \
        }                                                                 \
    }                                                                     \
} while (0)

// Fused 8-step GRU scan for one output iteration o.
// 4 lanes per node, TWO nodes per lane. Two-layer gate algebra folded:
// gate = sigma(P@M + H@L_bot + fb).
__global__ void __launch_bounds__(128)
k_scan(const float* __restrict__ att,
       const float* __restrict__ Lzw, const float* __restrict__ Lrw,
       const float* __restrict__ Lhw,
       const float* __restrict__ Wout, const float* __restrict__ bout,
       float* __restrict__ out, int N, int o)
{
    __shared__ __align__(16) float sMz[128], sMr[128], sMh[128];
    __shared__ __align__(16) float sLz[256], sLr[256], sLh[256];   // L bottom halves
    __shared__ __align__(16) float sfbz[16], sfbr[16], sfbh[16];
    __shared__ __align__(16) float sWo[128], sbo[8], sp[8];

    int tid = threadIdx.x;
    if (tid < 128) {
        sMz[tid] = g_M[tid]; sMr[tid] = g_M[128 + tid]; sMh[tid] = g_M[256 + tid];
        sWo[tid] = Wout[tid];
    }
    for (int i = tid; i < 256; i += 128) {
        sLz[i] = Lzw[256 + i]; sLr[i] = Lrw[256 + i]; sLh[i] = Lhw[256 + i];
    }
    if (tid < 16) {
        sfbz[tid] = g_fb[tid]; sfbr[tid] = g_fb[16 + tid]; sfbh[tid] = g_fb[32 + tid];
    }
    if (tid < 8) {
        sbo[tid] = bout[tid];
        float v = att[tid];
        float m = v;
        m = fmaxf(m, __shfl_xor_sync(0xffu, m, 1, 8));
        m = fmaxf(m, __shfl_xor_sync(0xffu, m, 2, 8));
        m = fmaxf(m, __shfl_xor_sync(0xffu, m, 4, 8));
        float e = __expf(v - m);
        float s = e;
        s += __shfl_xor_sync(0xffu, s, 1, 8);
        s += __shfl_xor_sync(0xffu, s, 2, 8);
        s += __shfl_xor_sync(0xffu, s, 4, 8);
        sp[tid] = __fdividef(e, s);
    }
    __syncthreads();

    int g = tid >> 2;
    int nodeA = blockIdx.x * 64 + g;
    int nodeB = nodeA + 32;
    bool validA = (nodeA < N);
    bool validB = (nodeB < N);
    if (nodeA >= N) nodeA = N - 1;
    if (nodeB >= N) nodeB = N - 1;
    int q  = tid & 3;
    int q4 = q * 4;

    float HA0 = 0.f, HA1 = 0.f, HA2 = 0.f, HA3 = 0.f;
    float HB0 = 0.f, HB1 = 0.f, HB2 = 0.f, HB3 = 0.f;
    float AA0 = 0.f, AA1 = 0.f, AA2 = 0.f, AA3 = 0.f;
    float AB0 = 0.f, AB1 = 0.f, AB2 = 0.f, AB3 = 0.f;

    const float* prowA = g_Px + (size_t)nodeA * ROWF + o * 8;
    const float* prowB = g_Px + (size_t)nodeB * ROWF + o * 8;

#pragma unroll 1
    for (int t = 0; t < 8; t++) {
        float4 qaA = ((const float4*)(prowA + t * 8))[0];
        float4 qbA = ((const float4*)(prowA + t * 8))[1];
        float4 qaB = ((const float4*)(prowB + t * 8))[0];
        float4 qbB = ((const float4*)(prowB + t * 8))[1];

        float hbA0, hbA1, hbA2, hbA3, hbA4, hbA5, hbA6, hbA7,
              hbA8, hbA9, hbA10, hbA11, hbA12, hbA13, hbA14, hbA15;
        float hbB0, hbB1, hbB2, hbB3, hbB4, hbB5, hbB6, hbB7,
              hbB8, hbB9, hbB10, hbB11, hbB12, hbB13, hbB14, hbB15;
        BCAST16(hbA, HA0, HA1, HA2, HA3);
        BCAST16(hbB, HB0, HB1, HB2, HB3);

        float ZA0, ZA1, ZA2, ZA3, ZB0, ZB1, ZB2, ZB3;
        float RA0, RA1, RA2, RA3, RB0, RB1, RB2, RB3;
        float TA0, TA1, TA2, TA3, TB0, TB1, TB2, TB3;

        {   // ---- z gate ----
            float4 bv = *(const float4*)(sfbz + q4);
            float cA0 = bv.x, cA1 = bv.y, cA2 = bv.z, cA3 = bv.w;
            float cB0 = bv.x, cB1 = bv.y, cB2 = bv.z, cB3 = bv.w;
            DOT8P2(sMz);
            DOT16H(sLz, hbA, hbB);
            ZA0 = sigmoid_f(cA0); ZA1 = sigmoid_f(cA1); ZA2 = sigmoid_f(cA2); ZA3 = sigmoid_f(cA3);
            ZB0 = sigmoid_f(cB0); ZB1 = sigmoid_f(cB1); ZB2 = sigmoid_f(cB2); ZB3 = sigmoid_f(cB3);
        }
        {   // ---- r gate -> H*R ----
            float4 bv = *(const float4*)(sfbr + q4);
            float cA0 = bv.x, cA1 = bv.y, cA2 = bv.z, cA3 = bv.w;
            float cB0 = bv.x, cB1 = bv.y, cB2 = bv.z, cB3 = bv.w;
            DOT8P2(sMr);
            DOT16H(sLr, hbA, hbB);
            RA0 = HA0 * sigmoid_f(cA0); RA1 = HA1 * sigmoid_f(cA1);
            RA2 = HA2 * sigmoid_f(cA2); RA3 = HA3 * sigmoid_f(cA3);
            RB0 = HB0 * sigmoid_f(cB0); RB1 = HB1 * sigmoid_f(cB1);
            RB2 = HB2 * sigmoid_f(cB2); RB3 = HB3 * sigmoid_f(cB3);
        }
        {   // ---- h gate ----
            BCAST16(hbA, RA0, RA1, RA2, RA3);   // reuse hb regs for H*R broadcast
            BCAST16(hbB, RB0, RB1, RB2, RB3);
            float4 bv = *(const float4*)(sfbh + q4);
            float cA0 = bv.x, cA1 = bv.y, cA2 = bv.z, cA3 = bv.w;
            float cB0 = bv.x, cB1 = bv.y, cB2 = bv.z, cB3 = bv.w;
            DOT8P2(sMh);
            DOT16H(sLh, hbA, hbB);
            TA0 = tanh_f(cA0); TA1 = tanh_f(cA1); TA2 = tanh_f(cA2); TA3 = tanh_f(cA3);
            TB0 = tanh_f(cB0); TB1 = tanh_f(cB1); TB2 = tanh_f(cB2); TB3 = tanh_f(cB3);
        }

        float pt = sp[t];
        HA0 = ZA0 * HA0 + (1.0f - ZA0) * TA0;  AA0 = fmaf(pt, HA0, AA0);
        HA1 = ZA1 * HA1 + (1.0f - ZA1) * TA1;  AA1 = fmaf(pt, HA1, AA1);
        HA2 = ZA2 * HA2 + (1.0f - ZA2) * TA2;  AA2 = fmaf(pt, HA2, AA2);
        HA3 = ZA3 * HA3 + (1.0f - ZA3) * TA3;  AA3 = fmaf(pt, HA3, AA3);
        HB0 = ZB0 * HB0 + (1.0f - ZB0) * TB0;  AB0 = fmaf(pt, HB0, AB0);
        HB1 = ZB1 * HB1 + (1.0f - ZB1) * TB1;  AB1 = fmaf(pt, HB1, AB1);
        HB2 = ZB2 * HB2 + (1.0f - ZB2) * TB2;  AB2 = fmaf(pt, HB2, AB2);
        HB3 = ZB3 * HB3 + (1.0f - ZB3) * TB3;  AB3 = fmaf(pt, HB3, AB3);
    }

#define OUTF(F) (fmaf(r0, sWo[(q4 + 0) * 8 + (F)],                        \
                 fmaf(r1, sWo[(q4 + 1) * 8 + (F)],                        \
                 fmaf(r2, sWo[(q4 + 2) * 8 + (F)],                        \
                      r3 * sWo[(q4 + 3) * 8 + (F)]))))
    EPILOGUE(AA0, AA1, AA2, AA3, nodeA, validA);
    EPILOGUE(AB0, AB1, AB2, AB3, nodeB, validB);
#undef OUTF
}

// ---------------------------------------------------------------------------
extern "C" void kernel_launch(void* const* d_in, const int* in_sizes, int n_in,
                              void* d_out, int out_size)
{
    const float* x    = (const float*)d_in[0];
    const int*   ei   = (const int*)d_in[1];
    const float* att  = (const float*)d_in[2];
    const float* Wz   = (const float*)d_in[3];
    const float* bz   = (const float*)d_in[4];
    const float* Lzw  = (const float*)d_in[5];
    const float* Lzb  = (const float*)d_in[6];
    const float* Wr   = (const float*)d_in[7];
    const float* br   = (const float*)d_in[8];
    const float* Lrw  = (const float*)d_in[9];
    const float* Lrb  = (const float*)d_in[10];
    const float* Wh   = (const float*)d_in[11];
    const float* bh   = (const float*)d_in[12];
    const float* Lhw  = (const float*)d_in[13];
    const float* Lhb  = (const float*)d_in[14];
    const float* Wout = (const float*)d_in[15];
    const float* bout = (const float*)d_in[16];
    float* out = (float*)d_out;

    int N = in_sizes[0] / (FND * TIN);
    int E = in_sizes[1] / 2;
    if (N > NN) N = NN;   // static scratch capacity guard
    if (E > EE) E = EE;

    const int TB = 256;
    // ---- CSR build + weight fold (once per launch) ----
    k_zero_int<<<(N + TB - 1) / TB, TB>>>(N);
    k_cnt<<<(E + TB - 1) / TB, TB>>>(ei, E);
    k_norm<<<(N + TB - 1) / TB, TB>>>(N);
    k_alloc<<<(N + 255) / 256, 256>>>(N);
    k_scatter<<<(E + TB - 1) / TB, TB>>>(ei, E);
    k_fold<<<1, 64>>>(Wz, bz, Lzw, Lzb, Wr, br, Lrw, Lrb, Wh, bh, Lhw, Lhb);
    // ---- initial propagation (gather, no atomics) ----
    {
        long long tot = (long long)N * 8;
        k_gather_init<<<(int)((tot + TB - 1) / TB), TB>>>(x, N);
    }

    for (int o = 0; o < TOUTN; o++) {
        k_scan<<<(N + 63) / 64, 128>>>(att, Lzw, Lrw, Lhw, Wout, bout, out, N, o);
        if (o < 3) {
            long long tot = (long long)N * 8;
            k_gather_h<<<(int)((tot + TB - 1) / TB), TB>>>(N, 8 + o);
        }
    }
}